// round 1
// baseline (speedup 1.0000x reference)
#include <cuda_runtime.h>
#include <cstdint>

// ---------------------------------------------------------------------------
// CasualSelfAttention: B=4, T=2048, C=2048, H=16, HD=128
//   qkv = x @ Wqkv ; rope(q,k) ; flash-attention (causal) ; out = y @ Wproj
// GEMMs: split-tf32 (hi+lo, 3 mma) for ~fp32 accuracy on mma.sync tensor cores.
// Attention: single-pass tf32 flash kernel with online softmax.
// ---------------------------------------------------------------------------

#define DEVINLINE __device__ __forceinline__

static constexpr int Bt = 4;
static constexpr int Tt = 2048;
static constexpr int Ct = 2048;
static constexpr int Ht = 16;
static constexpr int HDt = 128;
static constexpr int MTOT = Bt * Tt;        // 8192
static constexpr int C3 = 3 * Ct;           // 6144

// Scratch (device globals: allocation-free rule)
__device__ float g_qkv[(size_t)MTOT * C3];  // 201 MB
__device__ float g_y[(size_t)MTOT * Ct];    // 67 MB

DEVINLINE uint32_t f2tf(float f) {
    uint32_t u;
    asm("cvt.rna.tf32.f32 %0, %1;" : "=r"(u) : "f"(f));
    return u;
}

DEVINLINE void mma8(float* d, const uint32_t* a, const uint32_t* b) {
    asm volatile(
        "mma.sync.aligned.m16n8k8.row.col.f32.tf32.tf32.f32 "
        "{%0,%1,%2,%3}, {%4,%5,%6,%7}, {%8,%9}, {%0,%1,%2,%3};"
        : "+f"(d[0]), "+f"(d[1]), "+f"(d[2]), "+f"(d[3])
        : "r"(a[0]), "r"(a[1]), "r"(a[2]), "r"(a[3]), "r"(b[0]), "r"(b[1]));
}

// ---------------------------------------------------------------------------
// Split-tf32 GEMM: C[M,N] = A[M,K] @ B[K,N], all fp32 row-major.
// 128x128x16 block tile, 256 threads (8 warps, 2x4), warp tile 64x32.
// ---------------------------------------------------------------------------
__global__ __launch_bounds__(256, 1) void gemm_tf32x2(
    const float* __restrict__ A, const float* __restrict__ Bm,
    float* __restrict__ Cm, int M, int N, int K)
{
    __shared__ uint32_t Ah[128 * 20], Al[128 * 20];   // [m][k], stride 20 (conflict-free)
    __shared__ uint32_t Bh[16 * 136], Bl[16 * 136];   // [k][n], stride 136 (conflict-free)

    const int tid = threadIdx.x;
    const int w = tid >> 5, lane = tid & 31;
    const int wm = w >> 2, wn = w & 3;
    const int g = lane >> 2, tg = lane & 3;
    const int m0 = blockIdx.y * 128, n0 = blockIdx.x * 128;

    float acc[4][4][4];
#pragma unroll
    for (int mt = 0; mt < 4; ++mt)
#pragma unroll
        for (int nt = 0; nt < 4; ++nt)
#pragma unroll
            for (int q = 0; q < 4; ++q) acc[mt][nt][q] = 0.f;

    for (int kt = 0; kt < K; kt += 16) {
        float4 av[2], bv[2];
#pragma unroll
        for (int i = 0; i < 2; ++i) {
            int id = tid + i * 256;
            int r = id >> 2, c4 = (id & 3) * 4;
            av[i] = *(const float4*)(A + (size_t)(m0 + r) * K + kt + c4);
            int rb = id >> 5, cb = (id & 31) * 4;
            bv[i] = *(const float4*)(Bm + (size_t)(kt + rb) * N + n0 + cb);
        }
        __syncthreads();
#pragma unroll
        for (int i = 0; i < 2; ++i) {
            int id = tid + i * 256;
            int r = id >> 2, c4 = (id & 3) * 4;
            const float* pa = (const float*)&av[i];
#pragma unroll
            for (int j = 0; j < 4; ++j) {
                uint32_t hi = f2tf(pa[j]);
                uint32_t lo = f2tf(pa[j] - __uint_as_float(hi));
                Ah[r * 20 + c4 + j] = hi;
                Al[r * 20 + c4 + j] = lo;
            }
            int rb = id >> 5, cb = (id & 31) * 4;
            const float* pb = (const float*)&bv[i];
#pragma unroll
            for (int j = 0; j < 4; ++j) {
                uint32_t hi = f2tf(pb[j]);
                uint32_t lo = f2tf(pb[j] - __uint_as_float(hi));
                Bh[rb * 136 + cb + j] = hi;
                Bl[rb * 136 + cb + j] = lo;
            }
        }
        __syncthreads();

#pragma unroll
        for (int ks = 0; ks < 2; ++ks) {
            const int kb = ks * 8;
            uint32_t ah[4][4], alr[4][4], bh[4][2], blr[4][2];
#pragma unroll
            for (int mt = 0; mt < 4; ++mt) {
                int r = wm * 64 + mt * 16 + g;
                int c = kb + tg;
                ah[mt][0] = Ah[r * 20 + c];
                ah[mt][1] = Ah[(r + 8) * 20 + c];
                ah[mt][2] = Ah[r * 20 + c + 4];
                ah[mt][3] = Ah[(r + 8) * 20 + c + 4];
                alr[mt][0] = Al[r * 20 + c];
                alr[mt][1] = Al[(r + 8) * 20 + c];
                alr[mt][2] = Al[r * 20 + c + 4];
                alr[mt][3] = Al[(r + 8) * 20 + c + 4];
            }
#pragma unroll
            for (int nt = 0; nt < 4; ++nt) {
                int cc = wn * 32 + nt * 8 + g;
                int rk = kb + tg;
                bh[nt][0] = Bh[rk * 136 + cc];
                bh[nt][1] = Bh[(rk + 4) * 136 + cc];
                blr[nt][0] = Bl[rk * 136 + cc];
                blr[nt][1] = Bl[(rk + 4) * 136 + cc];
            }
#pragma unroll
            for (int mt = 0; mt < 4; ++mt)
#pragma unroll
                for (int nt = 0; nt < 4; ++nt) {
                    mma8(acc[mt][nt], ah[mt], bh[nt]);   // hi*hi
                    mma8(acc[mt][nt], ah[mt], blr[nt]);  // hi*lo
                    mma8(acc[mt][nt], alr[mt], bh[nt]);  // lo*hi
                }
        }
    }

#pragma unroll
    for (int mt = 0; mt < 4; ++mt)
#pragma unroll
        for (int nt = 0; nt < 4; ++nt) {
            int r = m0 + wm * 64 + mt * 16 + g;
            int c = n0 + wn * 32 + nt * 8 + tg * 2;
            *(float2*)(Cm + (size_t)r * N + c) =
                make_float2(acc[mt][nt][0], acc[mt][nt][1]);
            *(float2*)(Cm + (size_t)(r + 8) * N + c) =
                make_float2(acc[mt][nt][2], acc[mt][nt][3]);
        }
}

// ---------------------------------------------------------------------------
// RoPE, in-place on q and k halves of qkv.
// ---------------------------------------------------------------------------
__global__ void rope_kernel(float* __restrict__ qkv, const float* __restrict__ rope)
{
    int idx = blockIdx.x * blockDim.x + threadIdx.x;   // B*T*H*64 threads
    int d = idx & 63;
    int h = (idx >> 6) & 15;
    int m = idx >> 10;               // b*T + t
    int t = m & (Tt - 1);
    float cs = rope[(t * 64 + d) * 2 + 0];
    float sn = rope[(t * 64 + d) * 2 + 1];
    size_t base = (size_t)m * C3 + h * HDt + 2 * d;
    float2 q = *(float2*)(qkv + base);
    float2 k = *(float2*)(qkv + base + Ct);
    *(float2*)(qkv + base)      = make_float2(q.x * cs - q.y * sn, q.y * cs + q.x * sn);
    *(float2*)(qkv + base + Ct) = make_float2(k.x * cs - k.y * sn, k.y * cs + k.x * sn);
}

// ---------------------------------------------------------------------------
// Flash attention, tf32, causal. 1 block = (b, h, 64-row q tile). 128 threads.
// Smem strides chosen so all fragment loads are bank-conflict-free.
// ---------------------------------------------------------------------------
static constexpr int FLASH_SMEM_U32 = 64 * 132 + 64 * 132 + 64 * 136 + 64 * 68;
static constexpr int FLASH_SMEM = FLASH_SMEM_U32 * 4;  // 119808 B

__global__ __launch_bounds__(128, 1) void flash_kernel(
    const float* __restrict__ qkv, float* __restrict__ y)
{
    extern __shared__ uint32_t sm[];
    uint32_t* Qs = sm;                  // [64][132]
    uint32_t* Ks = Qs + 64 * 132;       // [64][132]  (row = kv, col = d)
    uint32_t* Vs = Ks + 64 * 132;       // [64][136]  (row = kv, col = d)
    uint32_t* Ps = Vs + 64 * 136;       // [64][68]

    const int tid = threadIdx.x;
    const int w = tid >> 5, lane = tid & 31;
    const int g = lane >> 2, tg = lane & 3;
    const int qt = blockIdx.x;
    const int bh = blockIdx.y;
    const int b = bh >> 4, h = bh & 15;
    const int q0 = qt * 64;
    const size_t rowbase = (size_t)(b * Tt) * C3;
    const int qcol = h * HDt, kcol = Ct + h * HDt;
    const int wr0 = w * 16;
    const float scale = 0.0883883476483184f;  // 1/sqrt(128)

    // Load Q tile (tf32-rounded)
#pragma unroll
    for (int i = 0; i < 16; ++i) {
        int id = tid + i * 128;
        int r = id >> 5, c = (id & 31) * 4;
        float4 v = *(const float4*)(qkv + rowbase + (size_t)(q0 + r) * C3 + qcol + c);
        Qs[r * 132 + c + 0] = f2tf(v.x);
        Qs[r * 132 + c + 1] = f2tf(v.y);
        Qs[r * 132 + c + 2] = f2tf(v.z);
        Qs[r * 132 + c + 3] = f2tf(v.w);
    }

    float m_a = -1e30f, m_b = -1e30f, l_a = 0.f, l_b = 0.f;
    float o[16][4];
#pragma unroll
    for (int nt = 0; nt < 16; ++nt)
#pragma unroll
        for (int q = 0; q < 4; ++q) o[nt][q] = 0.f;

    for (int j = 0; j <= qt; ++j) {
        const int kv0 = j * 64;
        __syncthreads();   // previous tile fully consumed; Q visible on first iter
#pragma unroll 4
        for (int i = 0; i < 16; ++i) {
            int id = tid + i * 128;
            int r = id >> 5, c = (id & 31) * 4;
            const float* kp = qkv + rowbase + (size_t)(kv0 + r) * C3 + kcol + c;
            float4 kv4 = *(const float4*)kp;
            float4 vv4 = *(const float4*)(kp + Ct);
            Ks[r * 132 + c + 0] = f2tf(kv4.x);
            Ks[r * 132 + c + 1] = f2tf(kv4.y);
            Ks[r * 132 + c + 2] = f2tf(kv4.z);
            Ks[r * 132 + c + 3] = f2tf(kv4.w);
            Vs[r * 136 + c + 0] = f2tf(vv4.x);
            Vs[r * 136 + c + 1] = f2tf(vv4.y);
            Vs[r * 136 + c + 2] = f2tf(vv4.z);
            Vs[r * 136 + c + 3] = f2tf(vv4.w);
        }
        __syncthreads();

        // S = Q @ K^T  (16x64 per warp)
        float s[8][4];
#pragma unroll
        for (int nt = 0; nt < 8; ++nt)
#pragma unroll
            for (int q = 0; q < 4; ++q) s[nt][q] = 0.f;
#pragma unroll
        for (int kk = 0; kk < 16; ++kk) {
            uint32_t a[4];
            int ar = (wr0 + g) * 132 + kk * 8 + tg;
            a[0] = Qs[ar];
            a[1] = Qs[ar + 8 * 132];
            a[2] = Qs[ar + 4];
            a[3] = Qs[ar + 8 * 132 + 4];
#pragma unroll
            for (int nt = 0; nt < 8; ++nt) {
                uint32_t bb[2];
                int br = (nt * 8 + g) * 132 + kk * 8 + tg;
                bb[0] = Ks[br];
                bb[1] = Ks[br + 4];
                mma8(s[nt], a, bb);
            }
        }

        // scale + causal mask (only the diagonal tile needs masking)
#pragma unroll
        for (int nt = 0; nt < 8; ++nt)
#pragma unroll
            for (int q = 0; q < 4; ++q) s[nt][q] *= scale;
        if (j == qt) {
            int ra = wr0 + g, rb = ra + 8;
#pragma unroll
            for (int nt = 0; nt < 8; ++nt) {
                int c0 = nt * 8 + tg * 2;
                if (c0     > ra) s[nt][0] = -1e30f;
                if (c0 + 1 > ra) s[nt][1] = -1e30f;
                if (c0     > rb) s[nt][2] = -1e30f;
                if (c0 + 1 > rb) s[nt][3] = -1e30f;
            }
        }

        // online softmax
        float tma = -1e30f, tmb = -1e30f;
#pragma unroll
        for (int nt = 0; nt < 8; ++nt) {
            tma = fmaxf(tma, fmaxf(s[nt][0], s[nt][1]));
            tmb = fmaxf(tmb, fmaxf(s[nt][2], s[nt][3]));
        }
        tma = fmaxf(tma, __shfl_xor_sync(0xffffffffu, tma, 1));
        tma = fmaxf(tma, __shfl_xor_sync(0xffffffffu, tma, 2));
        tmb = fmaxf(tmb, __shfl_xor_sync(0xffffffffu, tmb, 1));
        tmb = fmaxf(tmb, __shfl_xor_sync(0xffffffffu, tmb, 2));
        float mna = fmaxf(m_a, tma), mnb = fmaxf(m_b, tmb);
        float aa = __expf(m_a - mna), ab = __expf(m_b - mnb);
        float rsa = 0.f, rsb = 0.f;
#pragma unroll
        for (int nt = 0; nt < 8; ++nt) {
            s[nt][0] = __expf(s[nt][0] - mna);
            s[nt][1] = __expf(s[nt][1] - mna);
            s[nt][2] = __expf(s[nt][2] - mnb);
            s[nt][3] = __expf(s[nt][3] - mnb);
            rsa += s[nt][0] + s[nt][1];
            rsb += s[nt][2] + s[nt][3];
        }
        rsa += __shfl_xor_sync(0xffffffffu, rsa, 1);
        rsa += __shfl_xor_sync(0xffffffffu, rsa, 2);
        rsb += __shfl_xor_sync(0xffffffffu, rsb, 1);
        rsb += __shfl_xor_sync(0xffffffffu, rsb, 2);
        l_a = l_a * aa + rsa;
        l_b = l_b * ab + rsb;
        m_a = mna;
        m_b = mnb;
#pragma unroll
        for (int nt = 0; nt < 16; ++nt) {
            o[nt][0] *= aa; o[nt][1] *= aa;
            o[nt][2] *= ab; o[nt][3] *= ab;
        }

        // store P (tf32 bits) to per-warp smem region
#pragma unroll
        for (int nt = 0; nt < 8; ++nt) {
            int c0 = nt * 8 + tg * 2;
            Ps[(wr0 + g) * 68 + c0]     = f2tf(s[nt][0]);
            Ps[(wr0 + g) * 68 + c0 + 1] = f2tf(s[nt][1]);
            Ps[(wr0 + g + 8) * 68 + c0]     = f2tf(s[nt][2]);
            Ps[(wr0 + g + 8) * 68 + c0 + 1] = f2tf(s[nt][3]);
        }
        __syncwarp();

        // O += P @ V   (16x128 per warp)
#pragma unroll
        for (int kk = 0; kk < 8; ++kk) {
            uint32_t a[4];
            int ar = (wr0 + g) * 68 + kk * 8 + tg;
            a[0] = Ps[ar];
            a[1] = Ps[ar + 8 * 68];
            a[2] = Ps[ar + 4];
            a[3] = Ps[ar + 8 * 68 + 4];
#pragma unroll
            for (int nt = 0; nt < 16; ++nt) {
                uint32_t bb[2];
                int br = (kk * 8 + tg) * 136 + nt * 8 + g;
                bb[0] = Vs[br];
                bb[1] = Vs[br + 4 * 136];
                mma8(o[nt], a, bb);
            }
        }
    }

    // epilogue: normalize and write to y[B*T, C] at head column block
    float inva = 1.f / l_a, invb = 1.f / l_b;
    int ra_tok = b * Tt + q0 + wr0 + g;
#pragma unroll
    for (int nt = 0; nt < 16; ++nt) {
        int c = h * HDt + nt * 8 + tg * 2;
        *(float2*)(y + (size_t)ra_tok * Ct + c) =
            make_float2(o[nt][0] * inva, o[nt][1] * inva);
        *(float2*)(y + (size_t)(ra_tok + 8) * Ct + c) =
            make_float2(o[nt][2] * invb, o[nt][3] * invb);
    }
}

// ---------------------------------------------------------------------------
extern "C" void kernel_launch(void* const* d_in, const int* in_sizes, int n_in,
                              void* d_out, int out_size)
{
    const float* x     = (const float*)d_in[0];
    const float* rope  = (const float*)d_in[1];
    const float* Wqkv  = (const float*)d_in[2];
    const float* Wproj = (const float*)d_in[3];
    float* out = (float*)d_out;

    float *qkv, *y;
    cudaGetSymbolAddress((void**)&qkv, g_qkv);
    cudaGetSymbolAddress((void**)&y, g_y);

    // 1) qkv = x @ Wqkv   (M=8192, N=6144, K=2048)
    gemm_tf32x2<<<dim3(C3 / 128, MTOT / 128), 256>>>(x, Wqkv, qkv, MTOT, C3, Ct);

    // 2) RoPE in-place on q, k
    rope_kernel<<<(MTOT * Ht * (HDt / 2)) / 256, 256>>>(qkv, rope);

    // 3) flash attention -> y
    cudaFuncSetAttribute(flash_kernel, cudaFuncAttributeMaxDynamicSharedMemorySize,
                         FLASH_SMEM);
    flash_kernel<<<dim3(Tt / 64, Bt * Ht), 128, FLASH_SMEM>>>(qkv, y);

    // 4) out = y @ Wproj  (M=8192, N=2048, K=2048)
    gemm_tf32x2<<<dim3(Ct / 128, MTOT / 128), 256>>>(y, Wproj, out, MTOT, Ct, Ct);
}

// round 2
// speedup vs baseline: 1.0023x; 1.0023x over previous
#include <cuda_runtime.h>
#include <cstdint>

// ---------------------------------------------------------------------------
// CasualSelfAttention: B=4, T=2048, C=2048, H=16, HD=128
//   qkv = x @ Wqkv ; rope(q,k) ; flash-attention (causal) ; out = y @ Wproj
// GEMMs: split-tf32 (hi+lo, 3 mma) for ~fp32 accuracy on mma.sync tensor cores.
// Attention: single-pass tf32 flash kernel with online softmax.
// ---------------------------------------------------------------------------

#define DEVINLINE __device__ __forceinline__

static constexpr int Bt = 4;
static constexpr int Tt = 2048;
static constexpr int Ct = 2048;
static constexpr int Ht = 16;
static constexpr int HDt = 128;
static constexpr int MTOT = Bt * Tt;        // 8192
static constexpr int C3 = 3 * Ct;           // 6144

// Scratch (device globals: allocation-free rule)
__device__ float g_qkv[(size_t)MTOT * C3];  // 201 MB
__device__ float g_y[(size_t)MTOT * Ct];    // 67 MB

DEVINLINE uint32_t f2tf(float f) {
    uint32_t u;
    asm("cvt.rna.tf32.f32 %0, %1;" : "=r"(u) : "f"(f));
    return u;
}

DEVINLINE void mma8(float* d, const uint32_t* a, const uint32_t* b) {
    asm volatile(
        "mma.sync.aligned.m16n8k8.row.col.f32.tf32.tf32.f32 "
        "{%0,%1,%2,%3}, {%4,%5,%6,%7}, {%8,%9}, {%0,%1,%2,%3};"
        : "+f"(d[0]), "+f"(d[1]), "+f"(d[2]), "+f"(d[3])
        : "r"(a[0]), "r"(a[1]), "r"(a[2]), "r"(a[3]), "r"(b[0]), "r"(b[1]));
}

// ---------------------------------------------------------------------------
// Split-tf32 GEMM: C[M,N] = A[M,K] @ B[K,N], all fp32 row-major.
// 128x128x16 block tile, 256 threads (8 warps, 2x4), warp tile 64x32.
// ---------------------------------------------------------------------------
__global__ __launch_bounds__(256, 1) void gemm_tf32x2(
    const float* __restrict__ A, const float* __restrict__ Bm,
    float* __restrict__ Cm, int M, int N, int K)
{
    __shared__ uint32_t Ah[128 * 20], Al[128 * 20];   // [m][k], stride 20 (conflict-free)
    __shared__ uint32_t Bh[16 * 136], Bl[16 * 136];   // [k][n], stride 136 (conflict-free)

    const int tid = threadIdx.x;
    const int w = tid >> 5, lane = tid & 31;
    const int wm = w >> 2, wn = w & 3;
    const int g = lane >> 2, tg = lane & 3;
    const int m0 = blockIdx.y * 128, n0 = blockIdx.x * 128;

    float acc[4][4][4];
#pragma unroll
    for (int mt = 0; mt < 4; ++mt)
#pragma unroll
        for (int nt = 0; nt < 4; ++nt)
#pragma unroll
            for (int q = 0; q < 4; ++q) acc[mt][nt][q] = 0.f;

    for (int kt = 0; kt < K; kt += 16) {
        float4 av[2], bv[2];
#pragma unroll
        for (int i = 0; i < 2; ++i) {
            int id = tid + i * 256;
            int r = id >> 2, c4 = (id & 3) * 4;
            av[i] = *(const float4*)(A + (size_t)(m0 + r) * K + kt + c4);
            int rb = id >> 5, cb = (id & 31) * 4;
            bv[i] = *(const float4*)(Bm + (size_t)(kt + rb) * N + n0 + cb);
        }
        __syncthreads();
#pragma unroll
        for (int i = 0; i < 2; ++i) {
            int id = tid + i * 256;
            int r = id >> 2, c4 = (id & 3) * 4;
            const float* pa = (const float*)&av[i];
#pragma unroll
            for (int j = 0; j < 4; ++j) {
                uint32_t hi = f2tf(pa[j]);
                uint32_t lo = f2tf(pa[j] - __uint_as_float(hi));
                Ah[r * 20 + c4 + j] = hi;
                Al[r * 20 + c4 + j] = lo;
            }
            int rb = id >> 5, cb = (id & 31) * 4;
            const float* pb = (const float*)&bv[i];
#pragma unroll
            for (int j = 0; j < 4; ++j) {
                uint32_t hi = f2tf(pb[j]);
                uint32_t lo = f2tf(pb[j] - __uint_as_float(hi));
                Bh[rb * 136 + cb + j] = hi;
                Bl[rb * 136 + cb + j] = lo;
            }
        }
        __syncthreads();

#pragma unroll
        for (int ks = 0; ks < 2; ++ks) {
            const int kb = ks * 8;
            uint32_t ah[4][4], alr[4][4], bh[4][2], blr[4][2];
#pragma unroll
            for (int mt = 0; mt < 4; ++mt) {
                int r = wm * 64 + mt * 16 + g;
                int c = kb + tg;
                ah[mt][0] = Ah[r * 20 + c];
                ah[mt][1] = Ah[(r + 8) * 20 + c];
                ah[mt][2] = Ah[r * 20 + c + 4];
                ah[mt][3] = Ah[(r + 8) * 20 + c + 4];
                alr[mt][0] = Al[r * 20 + c];
                alr[mt][1] = Al[(r + 8) * 20 + c];
                alr[mt][2] = Al[r * 20 + c + 4];
                alr[mt][3] = Al[(r + 8) * 20 + c + 4];
            }
#pragma unroll
            for (int nt = 0; nt < 4; ++nt) {
                int cc = wn * 32 + nt * 8 + g;
                int rk = kb + tg;
                bh[nt][0] = Bh[rk * 136 + cc];
                bh[nt][1] = Bh[(rk + 4) * 136 + cc];
                blr[nt][0] = Bl[rk * 136 + cc];
                blr[nt][1] = Bl[(rk + 4) * 136 + cc];
            }
#pragma unroll
            for (int mt = 0; mt < 4; ++mt)
#pragma unroll
                for (int nt = 0; nt < 4; ++nt) {
                    mma8(acc[mt][nt], ah[mt], bh[nt]);   // hi*hi
                    mma8(acc[mt][nt], ah[mt], blr[nt]);  // hi*lo
                    mma8(acc[mt][nt], alr[mt], bh[nt]);  // lo*hi
                }
        }
    }

#pragma unroll
    for (int mt = 0; mt < 4; ++mt)
#pragma unroll
        for (int nt = 0; nt < 4; ++nt) {
            int r = m0 + wm * 64 + mt * 16 + g;
            int c = n0 + wn * 32 + nt * 8 + tg * 2;
            *(float2*)(Cm + (size_t)r * N + c) =
                make_float2(acc[mt][nt][0], acc[mt][nt][1]);
            *(float2*)(Cm + (size_t)(r + 8) * N + c) =
                make_float2(acc[mt][nt][2], acc[mt][nt][3]);
        }
}

// ---------------------------------------------------------------------------
// RoPE, in-place on q and k halves of qkv.
// ---------------------------------------------------------------------------
__global__ void rope_kernel(float* __restrict__ qkv, const float* __restrict__ rope)
{
    int idx = blockIdx.x * blockDim.x + threadIdx.x;   // B*T*H*64 threads
    int d = idx & 63;
    int h = (idx >> 6) & 15;
    int m = idx >> 10;               // b*T + t
    int t = m & (Tt - 1);
    float cs = rope[(t * 64 + d) * 2 + 0];
    float sn = rope[(t * 64 + d) * 2 + 1];
    size_t base = (size_t)m * C3 + h * HDt + 2 * d;
    float2 q = *(float2*)(qkv + base);
    float2 k = *(float2*)(qkv + base + Ct);
    *(float2*)(qkv + base)      = make_float2(q.x * cs - q.y * sn, q.y * cs + q.x * sn);
    *(float2*)(qkv + base + Ct) = make_float2(k.x * cs - k.y * sn, k.y * cs + k.x * sn);
}

// ---------------------------------------------------------------------------
// Flash attention, tf32, causal. 1 block = (b, h, 64-row q tile). 128 threads.
// Smem strides chosen so all fragment loads are bank-conflict-free.
// ---------------------------------------------------------------------------
static constexpr int FLASH_SMEM_U32 = 64 * 132 + 64 * 132 + 64 * 136 + 64 * 68;
static constexpr int FLASH_SMEM = FLASH_SMEM_U32 * 4;  // 119808 B

__global__ __launch_bounds__(128, 1) void flash_kernel(
    const float* __restrict__ qkv, float* __restrict__ y)
{
    extern __shared__ uint32_t sm[];
    uint32_t* Qs = sm;                  // [64][132]
    uint32_t* Ks = Qs + 64 * 132;       // [64][132]  (row = kv, col = d)
    uint32_t* Vs = Ks + 64 * 132;       // [64][136]  (row = kv, col = d)
    uint32_t* Ps = Vs + 64 * 136;       // [64][68]

    const int tid = threadIdx.x;
    const int w = tid >> 5, lane = tid & 31;
    const int g = lane >> 2, tg = lane & 3;
    const int qt = blockIdx.x;
    const int bh = blockIdx.y;
    const int b = bh >> 4, h = bh & 15;
    const int q0 = qt * 64;
    const size_t rowbase = (size_t)(b * Tt) * C3;
    const int qcol = h * HDt, kcol = Ct + h * HDt;
    const int wr0 = w * 16;
    const float scale = 0.0883883476483184f;  // 1/sqrt(128)

    // Load Q tile (tf32-rounded)
#pragma unroll
    for (int i = 0; i < 16; ++i) {
        int id = tid + i * 128;
        int r = id >> 5, c = (id & 31) * 4;
        float4 v = *(const float4*)(qkv + rowbase + (size_t)(q0 + r) * C3 + qcol + c);
        Qs[r * 132 + c + 0] = f2tf(v.x);
        Qs[r * 132 + c + 1] = f2tf(v.y);
        Qs[r * 132 + c + 2] = f2tf(v.z);
        Qs[r * 132 + c + 3] = f2tf(v.w);
    }

    float m_a = -1e30f, m_b = -1e30f, l_a = 0.f, l_b = 0.f;
    float o[16][4];
#pragma unroll
    for (int nt = 0; nt < 16; ++nt)
#pragma unroll
        for (int q = 0; q < 4; ++q) o[nt][q] = 0.f;

    for (int j = 0; j <= qt; ++j) {
        const int kv0 = j * 64;
        __syncthreads();   // previous tile fully consumed; Q visible on first iter
#pragma unroll 4
        for (int i = 0; i < 16; ++i) {
            int id = tid + i * 128;
            int r = id >> 5, c = (id & 31) * 4;
            const float* kp = qkv + rowbase + (size_t)(kv0 + r) * C3 + kcol + c;
            float4 kv4 = *(const float4*)kp;
            float4 vv4 = *(const float4*)(kp + Ct);
            Ks[r * 132 + c + 0] = f2tf(kv4.x);
            Ks[r * 132 + c + 1] = f2tf(kv4.y);
            Ks[r * 132 + c + 2] = f2tf(kv4.z);
            Ks[r * 132 + c + 3] = f2tf(kv4.w);
            Vs[r * 136 + c + 0] = f2tf(vv4.x);
            Vs[r * 136 + c + 1] = f2tf(vv4.y);
            Vs[r * 136 + c + 2] = f2tf(vv4.z);
            Vs[r * 136 + c + 3] = f2tf(vv4.w);
        }
        __syncthreads();

        // S = Q @ K^T  (16x64 per warp)
        float s[8][4];
#pragma unroll
        for (int nt = 0; nt < 8; ++nt)
#pragma unroll
            for (int q = 0; q < 4; ++q) s[nt][q] = 0.f;
#pragma unroll
        for (int kk = 0; kk < 16; ++kk) {
            uint32_t a[4];
            int ar = (wr0 + g) * 132 + kk * 8 + tg;
            a[0] = Qs[ar];
            a[1] = Qs[ar + 8 * 132];
            a[2] = Qs[ar + 4];
            a[3] = Qs[ar + 8 * 132 + 4];
#pragma unroll
            for (int nt = 0; nt < 8; ++nt) {
                uint32_t bb[2];
                int br = (nt * 8 + g) * 132 + kk * 8 + tg;
                bb[0] = Ks[br];
                bb[1] = Ks[br + 4];
                mma8(s[nt], a, bb);
            }
        }

        // scale + causal mask (only the diagonal tile needs masking)
#pragma unroll
        for (int nt = 0; nt < 8; ++nt)
#pragma unroll
            for (int q = 0; q < 4; ++q) s[nt][q] *= scale;
        if (j == qt) {
            int ra = wr0 + g, rb = ra + 8;
#pragma unroll
            for (int nt = 0; nt < 8; ++nt) {
                int c0 = nt * 8 + tg * 2;
                if (c0     > ra) s[nt][0] = -1e30f;
                if (c0 + 1 > ra) s[nt][1] = -1e30f;
                if (c0     > rb) s[nt][2] = -1e30f;
                if (c0 + 1 > rb) s[nt][3] = -1e30f;
            }
        }

        // online softmax
        float tma = -1e30f, tmb = -1e30f;
#pragma unroll
        for (int nt = 0; nt < 8; ++nt) {
            tma = fmaxf(tma, fmaxf(s[nt][0], s[nt][1]));
            tmb = fmaxf(tmb, fmaxf(s[nt][2], s[nt][3]));
        }
        tma = fmaxf(tma, __shfl_xor_sync(0xffffffffu, tma, 1));
        tma = fmaxf(tma, __shfl_xor_sync(0xffffffffu, tma, 2));
        tmb = fmaxf(tmb, __shfl_xor_sync(0xffffffffu, tmb, 1));
        tmb = fmaxf(tmb, __shfl_xor_sync(0xffffffffu, tmb, 2));
        float mna = fmaxf(m_a, tma), mnb = fmaxf(m_b, tmb);
        float aa = __expf(m_a - mna), ab = __expf(m_b - mnb);
        float rsa = 0.f, rsb = 0.f;
#pragma unroll
        for (int nt = 0; nt < 8; ++nt) {
            s[nt][0] = __expf(s[nt][0] - mna);
            s[nt][1] = __expf(s[nt][1] - mna);
            s[nt][2] = __expf(s[nt][2] - mnb);
            s[nt][3] = __expf(s[nt][3] - mnb);
            rsa += s[nt][0] + s[nt][1];
            rsb += s[nt][2] + s[nt][3];
        }
        rsa += __shfl_xor_sync(0xffffffffu, rsa, 1);
        rsa += __shfl_xor_sync(0xffffffffu, rsa, 2);
        rsb += __shfl_xor_sync(0xffffffffu, rsb, 1);
        rsb += __shfl_xor_sync(0xffffffffu, rsb, 2);
        l_a = l_a * aa + rsa;
        l_b = l_b * ab + rsb;
        m_a = mna;
        m_b = mnb;
#pragma unroll
        for (int nt = 0; nt < 16; ++nt) {
            o[nt][0] *= aa; o[nt][1] *= aa;
            o[nt][2] *= ab; o[nt][3] *= ab;
        }

        // store P (tf32 bits) to per-warp smem region
#pragma unroll
        for (int nt = 0; nt < 8; ++nt) {
            int c0 = nt * 8 + tg * 2;
            Ps[(wr0 + g) * 68 + c0]     = f2tf(s[nt][0]);
            Ps[(wr0 + g) * 68 + c0 + 1] = f2tf(s[nt][1]);
            Ps[(wr0 + g + 8) * 68 + c0]     = f2tf(s[nt][2]);
            Ps[(wr0 + g + 8) * 68 + c0 + 1] = f2tf(s[nt][3]);
        }
        __syncwarp();

        // O += P @ V   (16x128 per warp)
#pragma unroll
        for (int kk = 0; kk < 8; ++kk) {
            uint32_t a[4];
            int ar = (wr0 + g) * 68 + kk * 8 + tg;
            a[0] = Ps[ar];
            a[1] = Ps[ar + 8 * 68];
            a[2] = Ps[ar + 4];
            a[3] = Ps[ar + 8 * 68 + 4];
#pragma unroll
            for (int nt = 0; nt < 16; ++nt) {
                uint32_t bb[2];
                int br = (kk * 8 + tg) * 136 + nt * 8 + g;
                bb[0] = Vs[br];
                bb[1] = Vs[br + 4 * 136];
                mma8(o[nt], a, bb);
            }
        }
    }

    // epilogue: normalize and write to y[B*T, C] at head column block
    float inva = 1.f / l_a, invb = 1.f / l_b;
    int ra_tok = b * Tt + q0 + wr0 + g;
#pragma unroll
    for (int nt = 0; nt < 16; ++nt) {
        int c = h * HDt + nt * 8 + tg * 2;
        *(float2*)(y + (size_t)ra_tok * Ct + c) =
            make_float2(o[nt][0] * inva, o[nt][1] * inva);
        *(float2*)(y + (size_t)(ra_tok + 8) * Ct + c) =
            make_float2(o[nt][2] * invb, o[nt][3] * invb);
    }
}

// ---------------------------------------------------------------------------
extern "C" void kernel_launch(void* const* d_in, const int* in_sizes, int n_in,
                              void* d_out, int out_size)
{
    const float* x     = (const float*)d_in[0];
    const float* rope  = (const float*)d_in[1];
    const float* Wqkv  = (const float*)d_in[2];
    const float* Wproj = (const float*)d_in[3];
    float* out = (float*)d_out;

    float *qkv, *y;
    cudaGetSymbolAddress((void**)&qkv, g_qkv);
    cudaGetSymbolAddress((void**)&y, g_y);

    // 1) qkv = x @ Wqkv   (M=8192, N=6144, K=2048)
    gemm_tf32x2<<<dim3(C3 / 128, MTOT / 128), 256>>>(x, Wqkv, qkv, MTOT, C3, Ct);

    // 2) RoPE in-place on q, k
    rope_kernel<<<(MTOT * Ht * (HDt / 2)) / 256, 256>>>(qkv, rope);

    // 3) flash attention -> y
    cudaFuncSetAttribute(flash_kernel, cudaFuncAttributeMaxDynamicSharedMemorySize,
                         FLASH_SMEM);
    flash_kernel<<<dim3(Tt / 64, Bt * Ht), 128, FLASH_SMEM>>>(qkv, y);

    // 4) out = y @ Wproj  (M=8192, N=2048, K=2048)
    gemm_tf32x2<<<dim3(Ct / 128, MTOT / 128), 256>>>(y, Wproj, out, MTOT, Ct, Ct);
}

// round 3
// speedup vs baseline: 2.1475x; 2.1425x over previous
#include <cuda_runtime.h>
#include <cuda_bf16.h>
#include <cstdint>

// ---------------------------------------------------------------------------
// CasualSelfAttention: B=4, T=2048, C=2048, H=16, HD=128
//   qkv = x @ Wqkv ; rope(q,k) ; flash-attention (causal) ; out = y @ Wproj
// GEMMs: split-bf16 (hi+lo, 3x mma.m16n8k16) ~fp32 accuracy, cp.async
//        double-buffered. Split/transpose done in cheap pre-pass kernels.
// Attention: tf32 flash kernel, Q in registers -> 2 CTAs/SM.
// ---------------------------------------------------------------------------

#define DEVINLINE __device__ __forceinline__

static constexpr int Bt = 4;
static constexpr int Tt = 2048;
static constexpr int Ct = 2048;
static constexpr int Ht = 16;
static constexpr int HDt = 128;
static constexpr int MTOT = Bt * Tt;        // 8192
static constexpr int C3 = 3 * Ct;           // 6144

// Scratch (device globals: allocation-free rule)
__device__ float g_qkv[(size_t)MTOT * C3];            // 201 MB
__device__ __nv_bfloat16 g_xh[(size_t)MTOT * Ct];     // 32 MB
__device__ __nv_bfloat16 g_xl[(size_t)MTOT * Ct];
__device__ __nv_bfloat16 g_wqh[(size_t)C3 * Ct];      // 24 MB (transposed [N][K])
__device__ __nv_bfloat16 g_wql[(size_t)C3 * Ct];
__device__ __nv_bfloat16 g_wph[(size_t)Ct * Ct];      // 8 MB (transposed)
__device__ __nv_bfloat16 g_wpl[(size_t)Ct * Ct];
__device__ __nv_bfloat16 g_yh[(size_t)MTOT * Ct];     // 32 MB
__device__ __nv_bfloat16 g_yl[(size_t)MTOT * Ct];

DEVINLINE uint32_t f2tf(float f) {
    uint32_t u;
    asm("cvt.rna.tf32.f32 %0, %1;" : "=r"(u) : "f"(f));
    return u;
}

DEVINLINE void mma8(float* d, const uint32_t* a, const uint32_t* b) {
    asm volatile(
        "mma.sync.aligned.m16n8k8.row.col.f32.tf32.tf32.f32 "
        "{%0,%1,%2,%3}, {%4,%5,%6,%7}, {%8,%9}, {%0,%1,%2,%3};"
        : "+f"(d[0]), "+f"(d[1]), "+f"(d[2]), "+f"(d[3])
        : "r"(a[0]), "r"(a[1]), "r"(a[2]), "r"(a[3]), "r"(b[0]), "r"(b[1]));
}

DEVINLINE void mma16bf(float* d, const uint32_t* a, const uint32_t* b) {
    asm volatile(
        "mma.sync.aligned.m16n8k16.row.col.f32.bf16.bf16.f32 "
        "{%0,%1,%2,%3}, {%4,%5,%6,%7}, {%8,%9}, {%0,%1,%2,%3};"
        : "+f"(d[0]), "+f"(d[1]), "+f"(d[2]), "+f"(d[3])
        : "r"(a[0]), "r"(a[1]), "r"(a[2]), "r"(a[3]), "r"(b[0]), "r"(b[1]));
}

DEVINLINE void cpasync16(uint32_t saddr, const void* g) {
    asm volatile("cp.async.cg.shared.global [%0], [%1], 16;\n"
                 :: "r"(saddr), "l"(g));
}
DEVINLINE void cp_commit() { asm volatile("cp.async.commit_group;\n"); }
DEVINLINE void cp_wait1()  { asm volatile("cp.async.wait_group 1;\n"); }

DEVINLINE void split_bf16(float v, __nv_bfloat16& hi, __nv_bfloat16& lo) {
    hi = __float2bfloat16(v);
    lo = __float2bfloat16(v - __bfloat162float(hi));
}

// ---------------------------------------------------------------------------
// Pre-pass: elementwise fp32 -> (bf16 hi, bf16 lo)
// ---------------------------------------------------------------------------
__global__ void split_rows_kernel(const float* __restrict__ src,
                                  __nv_bfloat16* __restrict__ dh,
                                  __nv_bfloat16* __restrict__ dl, size_t n)
{
    size_t i = (size_t)blockIdx.x * blockDim.x + threadIdx.x;
    if (i >= n) return;
    __nv_bfloat16 h, l;
    split_bf16(src[i], h, l);
    dh[i] = h; dl[i] = l;
}

// Pre-pass: W[K][N] fp32 -> (hi, lo) bf16, transposed to [N][K]
__global__ void split_transpose_kernel(const float* __restrict__ W,
                                       __nv_bfloat16* __restrict__ th,
                                       __nv_bfloat16* __restrict__ tl,
                                       int K, int N)
{
    __shared__ float tile[32][33];
    int nx = blockIdx.x * 32, ky = blockIdx.y * 32;
    int tx = threadIdx.x, ty = threadIdx.y;   // 32 x 8
#pragma unroll
    for (int s = 0; s < 4; ++s)
        tile[ty + 8 * s][tx] = W[(size_t)(ky + ty + 8 * s) * N + nx + tx];
    __syncthreads();
#pragma unroll
    for (int s = 0; s < 4; ++s) {
        float v = tile[tx][ty + 8 * s];
        __nv_bfloat16 h, l;
        split_bf16(v, h, l);
        size_t idx = (size_t)(nx + ty + 8 * s) * K + ky + tx;
        th[idx] = h; tl[idx] = l;
    }
}

// ---------------------------------------------------------------------------
// Split-bf16 GEMM: C[M,N] = A[M,K] @ B^T (B given as [N][K]), all row-major.
// 128x128x32 block tile, 256 threads (8 warps 2x4), warp tile 64x32.
// cp.async double buffered. smem packed as u32 = bf16x2 along K, stride 20.
// ---------------------------------------------------------------------------
static constexpr int GEMM_STAGE_U32 = 128 * 20;              // per array per stage
static constexpr int GEMM_SMEM = 4 * 2 * GEMM_STAGE_U32 * 4; // 81920 B

__global__ __launch_bounds__(256, 1) void gemm_bf16x2(
    const __nv_bfloat16* __restrict__ Ah, const __nv_bfloat16* __restrict__ Al,
    const __nv_bfloat16* __restrict__ Bh, const __nv_bfloat16* __restrict__ Bl,
    float* __restrict__ Cm, int M, int N, int K)
{
    extern __shared__ uint32_t sm[];
    uint32_t* sAh = sm;                        // [2][128*20]
    uint32_t* sAl = sAh + 2 * GEMM_STAGE_U32;
    uint32_t* sBh = sAl + 2 * GEMM_STAGE_U32;
    uint32_t* sBl = sBh + 2 * GEMM_STAGE_U32;

    const int tid = threadIdx.x;
    const int w = tid >> 5, lane = tid & 31;
    const int wm = w >> 2, wn = w & 3;
    const int g = lane >> 2, tg = lane & 3;
    const int m0 = blockIdx.y * 128, n0 = blockIdx.x * 128;

    const uint32_t base_Ah = (uint32_t)__cvta_generic_to_shared(sAh);
    const uint32_t base_Al = (uint32_t)__cvta_generic_to_shared(sAl);
    const uint32_t base_Bh = (uint32_t)__cvta_generic_to_shared(sBh);
    const uint32_t base_Bl = (uint32_t)__cvta_generic_to_shared(sBl);

    // copy mapping: thread -> (row r, 16B-chunk c) covering 64 rows/pass
    const int cr = tid >> 2, cc = tid & 3;

    auto issue_tile = [&](int kt, int s) {
        const uint32_t soff = (uint32_t)s * GEMM_STAGE_U32 * 4;
#pragma unroll
        for (int half = 0; half < 2; ++half) {
            int r = cr + half * 64;
            uint32_t d = soff + (uint32_t)r * 80 + cc * 16;
            size_t ga = (size_t)(m0 + r) * K + kt + cc * 8;
            size_t gb = (size_t)(n0 + r) * K + kt + cc * 8;
            cpasync16(base_Ah + d, Ah + ga);
            cpasync16(base_Al + d, Al + ga);
            cpasync16(base_Bh + d, Bh + gb);
            cpasync16(base_Bl + d, Bl + gb);
        }
    };

    float acc[4][4][4];
#pragma unroll
    for (int mt = 0; mt < 4; ++mt)
#pragma unroll
        for (int nt = 0; nt < 4; ++nt)
#pragma unroll
            for (int q = 0; q < 4; ++q) acc[mt][nt][q] = 0.f;

    const int ntiles = K / 32;
    issue_tile(0, 0); cp_commit();
    issue_tile(32, 1); cp_commit();
    cp_wait1();
    __syncthreads();

    for (int t = 0; t < ntiles; ++t) {
        const uint32_t* cAh = sAh + (t & 1) * GEMM_STAGE_U32;
        const uint32_t* cAl = sAl + (t & 1) * GEMM_STAGE_U32;
        const uint32_t* cBh = sBh + (t & 1) * GEMM_STAGE_U32;
        const uint32_t* cBl = sBl + (t & 1) * GEMM_STAGE_U32;

#pragma unroll
        for (int ks = 0; ks < 2; ++ks) {
            const int kb = ks * 8;
            uint32_t ah[4][4], al[4][4], bh[4][2], bl[4][2];
#pragma unroll
            for (int mt = 0; mt < 4; ++mt) {
                int r = wm * 64 + mt * 16 + g;
                int i0 = r * 20 + kb + tg;
                int i1 = (r + 8) * 20 + kb + tg;
                ah[mt][0] = cAh[i0];     ah[mt][1] = cAh[i1];
                ah[mt][2] = cAh[i0 + 4]; ah[mt][3] = cAh[i1 + 4];
                al[mt][0] = cAl[i0];     al[mt][1] = cAl[i1];
                al[mt][2] = cAl[i0 + 4]; al[mt][3] = cAl[i1 + 4];
            }
#pragma unroll
            for (int nt = 0; nt < 4; ++nt) {
                int n = wn * 32 + nt * 8 + g;
                int i0 = n * 20 + kb + tg;
                bh[nt][0] = cBh[i0]; bh[nt][1] = cBh[i0 + 4];
                bl[nt][0] = cBl[i0]; bl[nt][1] = cBl[i0 + 4];
            }
#pragma unroll
            for (int mt = 0; mt < 4; ++mt)
#pragma unroll
                for (int nt = 0; nt < 4; ++nt) {
                    mma16bf(acc[mt][nt], ah[mt], bh[nt]);  // hi*hi
                    mma16bf(acc[mt][nt], ah[mt], bl[nt]);  // hi*lo
                    mma16bf(acc[mt][nt], al[mt], bh[nt]);  // lo*hi
                }
        }

        __syncthreads();                     // everyone done with buf t&1
        if (t + 2 < ntiles) issue_tile((t + 2) * 32, t & 1);
        cp_commit();
        cp_wait1();                          // tile t+1 landed
        __syncthreads();
    }

#pragma unroll
    for (int mt = 0; mt < 4; ++mt)
#pragma unroll
        for (int nt = 0; nt < 4; ++nt) {
            int r = m0 + wm * 64 + mt * 16 + g;
            int c = n0 + wn * 32 + nt * 8 + tg * 2;
            *(float2*)(Cm + (size_t)r * N + c) =
                make_float2(acc[mt][nt][0], acc[mt][nt][1]);
            *(float2*)(Cm + (size_t)(r + 8) * N + c) =
                make_float2(acc[mt][nt][2], acc[mt][nt][3]);
        }
}

// ---------------------------------------------------------------------------
// RoPE, in-place on q and k halves of qkv.
// ---------------------------------------------------------------------------
__global__ void rope_kernel(float* __restrict__ qkv, const float* __restrict__ rope)
{
    int idx = blockIdx.x * blockDim.x + threadIdx.x;   // B*T*H*64 threads
    int d = idx & 63;
    int h = (idx >> 6) & 15;
    int m = idx >> 10;               // b*T + t
    int t = m & (Tt - 1);
    float cs = rope[(t * 64 + d) * 2 + 0];
    float sn = rope[(t * 64 + d) * 2 + 1];
    size_t base = (size_t)m * C3 + h * HDt + 2 * d;
    float2 q = *(float2*)(qkv + base);
    float2 k = *(float2*)(qkv + base + Ct);
    *(float2*)(qkv + base)      = make_float2(q.x * cs - q.y * sn, q.y * cs + q.x * sn);
    *(float2*)(qkv + base + Ct) = make_float2(k.x * cs - k.y * sn, k.y * cs + k.x * sn);
}

// ---------------------------------------------------------------------------
// Flash attention, tf32, causal. 1 block = (b, h, 64-row q tile). 128 threads.
// Q fragments live in registers; smem = K,V,P only -> 2 CTAs/SM.
// Epilogue writes y as split bf16 (feeds GEMM2 directly).
// ---------------------------------------------------------------------------
static constexpr int FLASH_SMEM_U32 = 64 * 132 + 64 * 132 + 64 * 68;
static constexpr int FLASH_SMEM = FLASH_SMEM_U32 * 4;  // 84992 B

__global__ __launch_bounds__(128, 2) void flash_kernel(
    const float* __restrict__ qkv,
    __nv_bfloat16* __restrict__ yh, __nv_bfloat16* __restrict__ yl)
{
    extern __shared__ uint32_t sm[];
    uint32_t* Ks = sm;                  // [64][132]  (row = kv, col = d)
    uint32_t* Vs = Ks + 64 * 132;       // [64][132]  (row = kv, col = d)
    uint32_t* Ps = Vs + 64 * 132;       // [64][68]

    const int tid = threadIdx.x;
    const int w = tid >> 5, lane = tid & 31;
    const int g = lane >> 2, tg = lane & 3;
    const int qt = blockIdx.x;
    const int bh = blockIdx.y;
    const int b = bh >> 4, h = bh & 15;
    const int q0 = qt * 64;
    const size_t rowbase = (size_t)(b * Tt) * C3;
    const int qcol = h * HDt, kcol = Ct + h * HDt;
    const int wr0 = w * 16;
    const float scale = 0.0883883476483184f;  // 1/sqrt(128)

    // Stage Q tile through Ks, pull fragments into registers
#pragma unroll
    for (int i = 0; i < 16; ++i) {
        int id = tid + i * 128;
        int r = id >> 5, c = (id & 31) * 4;
        float4 v = *(const float4*)(qkv + rowbase + (size_t)(q0 + r) * C3 + qcol + c);
        Ks[r * 132 + c + 0] = f2tf(v.x);
        Ks[r * 132 + c + 1] = f2tf(v.y);
        Ks[r * 132 + c + 2] = f2tf(v.z);
        Ks[r * 132 + c + 3] = f2tf(v.w);
    }
    __syncthreads();
    uint32_t qf[16][4];
#pragma unroll
    for (int kk = 0; kk < 16; ++kk) {
        int ar = (wr0 + g) * 132 + kk * 8 + tg;
        qf[kk][0] = Ks[ar];
        qf[kk][1] = Ks[ar + 8 * 132];
        qf[kk][2] = Ks[ar + 4];
        qf[kk][3] = Ks[ar + 8 * 132 + 4];
    }

    float m_a = -1e30f, m_b = -1e30f, l_a = 0.f, l_b = 0.f;
    float o[16][4];
#pragma unroll
    for (int nt = 0; nt < 16; ++nt)
#pragma unroll
        for (int q = 0; q < 4; ++q) o[nt][q] = 0.f;

    for (int j = 0; j <= qt; ++j) {
        const int kv0 = j * 64;
        __syncthreads();   // previous tile (or Q frags) fully consumed
#pragma unroll 4
        for (int i = 0; i < 16; ++i) {
            int id = tid + i * 128;
            int r = id >> 5, c = (id & 31) * 4;
            const float* kp = qkv + rowbase + (size_t)(kv0 + r) * C3 + kcol + c;
            float4 kv4 = *(const float4*)kp;
            float4 vv4 = *(const float4*)(kp + Ct);
            Ks[r * 132 + c + 0] = f2tf(kv4.x);
            Ks[r * 132 + c + 1] = f2tf(kv4.y);
            Ks[r * 132 + c + 2] = f2tf(kv4.z);
            Ks[r * 132 + c + 3] = f2tf(kv4.w);
            Vs[r * 132 + c + 0] = f2tf(vv4.x);
            Vs[r * 132 + c + 1] = f2tf(vv4.y);
            Vs[r * 132 + c + 2] = f2tf(vv4.z);
            Vs[r * 132 + c + 3] = f2tf(vv4.w);
        }
        __syncthreads();

        // S = Q @ K^T  (16x64 per warp)
        float s[8][4];
#pragma unroll
        for (int nt = 0; nt < 8; ++nt)
#pragma unroll
            for (int q = 0; q < 4; ++q) s[nt][q] = 0.f;
#pragma unroll
        for (int kk = 0; kk < 16; ++kk) {
#pragma unroll
            for (int nt = 0; nt < 8; ++nt) {
                uint32_t bb[2];
                int br = (nt * 8 + g) * 132 + kk * 8 + tg;
                bb[0] = Ks[br];
                bb[1] = Ks[br + 4];
                mma8(s[nt], qf[kk], bb);
            }
        }

        // scale + causal mask (only the diagonal tile needs masking)
#pragma unroll
        for (int nt = 0; nt < 8; ++nt)
#pragma unroll
            for (int q = 0; q < 4; ++q) s[nt][q] *= scale;
        if (j == qt) {
            int ra = wr0 + g, rb = ra + 8;
#pragma unroll
            for (int nt = 0; nt < 8; ++nt) {
                int c0 = nt * 8 + tg * 2;
                if (c0     > ra) s[nt][0] = -1e30f;
                if (c0 + 1 > ra) s[nt][1] = -1e30f;
                if (c0     > rb) s[nt][2] = -1e30f;
                if (c0 + 1 > rb) s[nt][3] = -1e30f;
            }
        }

        // online softmax
        float tma = -1e30f, tmb = -1e30f;
#pragma unroll
        for (int nt = 0; nt < 8; ++nt) {
            tma = fmaxf(tma, fmaxf(s[nt][0], s[nt][1]));
            tmb = fmaxf(tmb, fmaxf(s[nt][2], s[nt][3]));
        }
        tma = fmaxf(tma, __shfl_xor_sync(0xffffffffu, tma, 1));
        tma = fmaxf(tma, __shfl_xor_sync(0xffffffffu, tma, 2));
        tmb = fmaxf(tmb, __shfl_xor_sync(0xffffffffu, tmb, 1));
        tmb = fmaxf(tmb, __shfl_xor_sync(0xffffffffu, tmb, 2));
        float mna = fmaxf(m_a, tma), mnb = fmaxf(m_b, tmb);
        float aa = __expf(m_a - mna), ab = __expf(m_b - mnb);
        float rsa = 0.f, rsb = 0.f;
#pragma unroll
        for (int nt = 0; nt < 8; ++nt) {
            s[nt][0] = __expf(s[nt][0] - mna);
            s[nt][1] = __expf(s[nt][1] - mna);
            s[nt][2] = __expf(s[nt][2] - mnb);
            s[nt][3] = __expf(s[nt][3] - mnb);
            rsa += s[nt][0] + s[nt][1];
            rsb += s[nt][2] + s[nt][3];
        }
        rsa += __shfl_xor_sync(0xffffffffu, rsa, 1);
        rsa += __shfl_xor_sync(0xffffffffu, rsa, 2);
        rsb += __shfl_xor_sync(0xffffffffu, rsb, 1);
        rsb += __shfl_xor_sync(0xffffffffu, rsb, 2);
        l_a = l_a * aa + rsa;
        l_b = l_b * ab + rsb;
        m_a = mna;
        m_b = mnb;
#pragma unroll
        for (int nt = 0; nt < 16; ++nt) {
            o[nt][0] *= aa; o[nt][1] *= aa;
            o[nt][2] *= ab; o[nt][3] *= ab;
        }

        // store P (tf32 bits) to per-warp smem region
#pragma unroll
        for (int nt = 0; nt < 8; ++nt) {
            int c0 = nt * 8 + tg * 2;
            Ps[(wr0 + g) * 68 + c0]     = f2tf(s[nt][0]);
            Ps[(wr0 + g) * 68 + c0 + 1] = f2tf(s[nt][1]);
            Ps[(wr0 + g + 8) * 68 + c0]     = f2tf(s[nt][2]);
            Ps[(wr0 + g + 8) * 68 + c0 + 1] = f2tf(s[nt][3]);
        }
        __syncwarp();

        // O += P @ V   (16x128 per warp)
#pragma unroll
        for (int kk = 0; kk < 8; ++kk) {
            uint32_t a[4];
            int ar = (wr0 + g) * 68 + kk * 8 + tg;
            a[0] = Ps[ar];
            a[1] = Ps[ar + 8 * 68];
            a[2] = Ps[ar + 4];
            a[3] = Ps[ar + 8 * 68 + 4];
#pragma unroll
            for (int nt = 0; nt < 16; ++nt) {
                uint32_t bb[2];
                int br = (kk * 8 + tg) * 132 + nt * 8 + g;
                bb[0] = Vs[br];
                bb[1] = Vs[br + 4 * 132];
                mma8(o[nt], a, bb);
            }
        }
    }

    // epilogue: normalize and write split-bf16 y (feeds GEMM2 directly)
    float inva = 1.f / l_a, invb = 1.f / l_b;
    int ra_tok = b * Tt + q0 + wr0 + g;
#pragma unroll
    for (int nt = 0; nt < 16; ++nt) {
        int c = h * HDt + nt * 8 + tg * 2;
        float va0 = o[nt][0] * inva, va1 = o[nt][1] * inva;
        float vb0 = o[nt][2] * invb, vb1 = o[nt][3] * invb;
        __nv_bfloat16 h0, l0, h1, l1;
        split_bf16(va0, h0, l0); split_bf16(va1, h1, l1);
        *(__nv_bfloat162*)(yh + (size_t)ra_tok * Ct + c) = __nv_bfloat162(h0, h1);
        *(__nv_bfloat162*)(yl + (size_t)ra_tok * Ct + c) = __nv_bfloat162(l0, l1);
        split_bf16(vb0, h0, l0); split_bf16(vb1, h1, l1);
        *(__nv_bfloat162*)(yh + (size_t)(ra_tok + 8) * Ct + c) = __nv_bfloat162(h0, h1);
        *(__nv_bfloat162*)(yl + (size_t)(ra_tok + 8) * Ct + c) = __nv_bfloat162(l0, l1);
    }
}

// ---------------------------------------------------------------------------
extern "C" void kernel_launch(void* const* d_in, const int* in_sizes, int n_in,
                              void* d_out, int out_size)
{
    const float* x     = (const float*)d_in[0];
    const float* rope  = (const float*)d_in[1];
    const float* Wqkv  = (const float*)d_in[2];
    const float* Wproj = (const float*)d_in[3];
    float* out = (float*)d_out;

    float* qkv;
    __nv_bfloat16 *xh, *xl, *wqh, *wql, *wph, *wpl, *yh, *yl;
    cudaGetSymbolAddress((void**)&qkv, g_qkv);
    cudaGetSymbolAddress((void**)&xh, g_xh);
    cudaGetSymbolAddress((void**)&xl, g_xl);
    cudaGetSymbolAddress((void**)&wqh, g_wqh);
    cudaGetSymbolAddress((void**)&wql, g_wql);
    cudaGetSymbolAddress((void**)&wph, g_wph);
    cudaGetSymbolAddress((void**)&wpl, g_wpl);
    cudaGetSymbolAddress((void**)&yh, g_yh);
    cudaGetSymbolAddress((void**)&yl, g_yl);

    cudaFuncSetAttribute(gemm_bf16x2, cudaFuncAttributeMaxDynamicSharedMemorySize,
                         GEMM_SMEM);
    cudaFuncSetAttribute(flash_kernel, cudaFuncAttributeMaxDynamicSharedMemorySize,
                         FLASH_SMEM);

    // 0) split/transpose pre-pass
    {
        size_t nx = (size_t)MTOT * Ct;
        split_rows_kernel<<<(unsigned)((nx + 255) / 256), 256>>>(x, xh, xl, nx);
        split_transpose_kernel<<<dim3(C3 / 32, Ct / 32), dim3(32, 8)>>>(Wqkv, wqh, wql, Ct, C3);
        split_transpose_kernel<<<dim3(Ct / 32, Ct / 32), dim3(32, 8)>>>(Wproj, wph, wpl, Ct, Ct);
    }

    // 1) qkv = x @ Wqkv   (M=8192, N=6144, K=2048)
    gemm_bf16x2<<<dim3(C3 / 128, MTOT / 128), 256, GEMM_SMEM>>>(
        xh, xl, wqh, wql, qkv, MTOT, C3, Ct);

    // 2) RoPE in-place on q, k
    rope_kernel<<<(MTOT * Ht * (HDt / 2)) / 256, 256>>>(qkv, rope);

    // 3) flash attention -> y (split bf16)
    flash_kernel<<<dim3(Tt / 64, Bt * Ht), 128, FLASH_SMEM>>>(qkv, yh, yl);

    // 4) out = y @ Wproj  (M=8192, N=2048, K=2048)
    gemm_bf16x2<<<dim3(Ct / 128, MTOT / 128), 256, GEMM_SMEM>>>(
        yh, yl, wph, wpl, out, MTOT, Ct, Ct);
}

// round 5
// speedup vs baseline: 2.4137x; 1.1240x over previous
#include <cuda_runtime.h>
#include <cuda_bf16.h>
#include <cstdint>

// ---------------------------------------------------------------------------
// CasualSelfAttention: B=4, T=2048, C=2048, H=16, HD=128
//   qkv = x @ Wqkv ; rope(q,k) ; flash-attention (causal) ; out = y @ Wproj
// GEMMs: split-bf16 (hi+lo, 3x mma.m16n8k16), cp.async double-buffered,
//        CTA tile 128x256, warp tile 64x64, K-tile 64.
// Attention: tf32 flash kernel, 128 q-rows/CTA (8 warps), Q in registers.
// ---------------------------------------------------------------------------

#define DEVINLINE __device__ __forceinline__

static constexpr int Bt = 4;
static constexpr int Tt = 2048;
static constexpr int Ct = 2048;
static constexpr int Ht = 16;
static constexpr int HDt = 128;
static constexpr int MTOT = Bt * Tt;        // 8192
static constexpr int C3 = 3 * Ct;           // 6144

// Scratch (device globals: allocation-free rule)
__device__ float g_qkv[(size_t)MTOT * C3];            // 201 MB
__device__ __nv_bfloat16 g_xh[(size_t)MTOT * Ct];
__device__ __nv_bfloat16 g_xl[(size_t)MTOT * Ct];
__device__ __nv_bfloat16 g_wqh[(size_t)C3 * Ct];      // transposed [N][K]
__device__ __nv_bfloat16 g_wql[(size_t)C3 * Ct];
__device__ __nv_bfloat16 g_wph[(size_t)Ct * Ct];      // transposed [N][K]
__device__ __nv_bfloat16 g_wpl[(size_t)Ct * Ct];
__device__ __nv_bfloat16 g_yh[(size_t)MTOT * Ct];
__device__ __nv_bfloat16 g_yl[(size_t)MTOT * Ct];

DEVINLINE uint32_t f2tf(float f) {
    uint32_t u;
    asm("cvt.rna.tf32.f32 %0, %1;" : "=r"(u) : "f"(f));
    return u;
}

DEVINLINE void mma8(float* d, const uint32_t* a, const uint32_t* b) {
    asm volatile(
        "mma.sync.aligned.m16n8k8.row.col.f32.tf32.tf32.f32 "
        "{%0,%1,%2,%3}, {%4,%5,%6,%7}, {%8,%9}, {%0,%1,%2,%3};"
        : "+f"(d[0]), "+f"(d[1]), "+f"(d[2]), "+f"(d[3])
        : "r"(a[0]), "r"(a[1]), "r"(a[2]), "r"(a[3]), "r"(b[0]), "r"(b[1]));
}

DEVINLINE void mma16bf(float* d, const uint32_t* a, const uint32_t* b) {
    asm volatile(
        "mma.sync.aligned.m16n8k16.row.col.f32.bf16.bf16.f32 "
        "{%0,%1,%2,%3}, {%4,%5,%6,%7}, {%8,%9}, {%0,%1,%2,%3};"
        : "+f"(d[0]), "+f"(d[1]), "+f"(d[2]), "+f"(d[3])
        : "r"(a[0]), "r"(a[1]), "r"(a[2]), "r"(a[3]), "r"(b[0]), "r"(b[1]));
}

DEVINLINE void cpasync16(uint32_t saddr, const void* g) {
    asm volatile("cp.async.cg.shared.global [%0], [%1], 16;\n"
                 :: "r"(saddr), "l"(g));
}
DEVINLINE void cp_commit() { asm volatile("cp.async.commit_group;\n"); }
DEVINLINE void cp_wait1()  { asm volatile("cp.async.wait_group 1;\n" ::: "memory"); }

DEVINLINE void split_bf16(float v, __nv_bfloat16& hi, __nv_bfloat16& lo) {
    hi = __float2bfloat16(v);
    lo = __float2bfloat16(v - __bfloat162float(hi));
}

// ---------------------------------------------------------------------------
// Pre-pass kernels
// ---------------------------------------------------------------------------
__global__ void split_rows_kernel(const float* __restrict__ src,
                                  __nv_bfloat16* __restrict__ dh,
                                  __nv_bfloat16* __restrict__ dl, size_t n)
{
    size_t i = (size_t)blockIdx.x * blockDim.x + threadIdx.x;
    if (i >= n) return;
    __nv_bfloat16 h, l;
    split_bf16(src[i], h, l);
    dh[i] = h; dl[i] = l;
}

__global__ void split_transpose_kernel(const float* __restrict__ W,
                                       __nv_bfloat16* __restrict__ th,
                                       __nv_bfloat16* __restrict__ tl,
                                       int K, int N)
{
    __shared__ float tile[32][33];
    int nx = blockIdx.x * 32, ky = blockIdx.y * 32;
    int tx = threadIdx.x, ty = threadIdx.y;   // 32 x 8
#pragma unroll
    for (int s = 0; s < 4; ++s)
        tile[ty + 8 * s][tx] = W[(size_t)(ky + ty + 8 * s) * N + nx + tx];
    __syncthreads();
#pragma unroll
    for (int s = 0; s < 4; ++s) {
        float v = tile[tx][ty + 8 * s];
        __nv_bfloat16 h, l;
        split_bf16(v, h, l);
        size_t idx = (size_t)(nx + ty + 8 * s) * K + ky + tx;
        th[idx] = h; tl[idx] = l;
    }
}

// ---------------------------------------------------------------------------
// Split-bf16 GEMM: C[M,N] = A[M,K] @ B^T (B given as [N][K]).
// CTA tile 128x256, 8 warps (2x4), warp tile 64x64, K-tile 64.
// cp.async double buffered. u32 = bf16x2 along K, row stride 36 u32.
// ---------------------------------------------------------------------------
static constexpr int GAST = 36;                      // u32 row stride
static constexpr int GA_U32 = 128 * GAST;            // 4608 per A array
static constexpr int GB_U32 = 256 * GAST;            // 9216 per B array
static constexpr int GSTG_U32 = 2 * GA_U32 + 2 * GB_U32;  // 27648 per stage
static constexpr int GEMM_SMEM = 2 * GSTG_U32 * 4;   // 221184 B

__global__ __launch_bounds__(256, 1) void gemm_bf16x2(
    const __nv_bfloat16* __restrict__ Ah, const __nv_bfloat16* __restrict__ Al,
    const __nv_bfloat16* __restrict__ Bh, const __nv_bfloat16* __restrict__ Bl,
    float* __restrict__ Cm, int M, int N, int K)
{
    extern __shared__ uint32_t sm[];

    const int tid = threadIdx.x;
    const int w = tid >> 5, lane = tid & 31;
    const int wm = w >> 2, wn = w & 3;          // 2 x 4 warps
    const int g = lane >> 2, tg = lane & 3;
    const int m0 = blockIdx.y * 128, n0 = blockIdx.x * 256;

    const uint32_t sbase = (uint32_t)__cvta_generic_to_shared(sm);

    auto issue_stage = [&](int kt, int s) {
        const uint32_t st = sbase + (uint32_t)s * GSTG_U32 * 4;
        const uint32_t stAh = st;
        const uint32_t stAl = st + GA_U32 * 4;
        const uint32_t stBh = st + 2 * GA_U32 * 4;
        const uint32_t stBl = st + 2 * GA_U32 * 4 + GB_U32 * 4;
#pragma unroll
        for (int i = 0; i < 4; ++i) {            // A: 1024 16B-chunks
            int id = tid + i * 256;
            int r = id >> 3, c = id & 7;
            uint32_t d = (uint32_t)r * (GAST * 4) + c * 16;
            size_t ga = (size_t)(m0 + r) * K + kt + c * 8;
            cpasync16(stAh + d, Ah + ga);
            cpasync16(stAl + d, Al + ga);
        }
#pragma unroll
        for (int i = 0; i < 8; ++i) {            // B: 2048 16B-chunks
            int id = tid + i * 256;
            int r = id >> 3, c = id & 7;
            uint32_t d = (uint32_t)r * (GAST * 4) + c * 16;
            size_t gb = (size_t)(n0 + r) * K + kt + c * 8;
            cpasync16(stBh + d, Bh + gb);
            cpasync16(stBl + d, Bl + gb);
        }
    };

    float acc[4][8][4];
#pragma unroll
    for (int mt = 0; mt < 4; ++mt)
#pragma unroll
        for (int nt = 0; nt < 8; ++nt)
#pragma unroll
            for (int q = 0; q < 4; ++q) acc[mt][nt][q] = 0.f;

    const int ntiles = K / 64;
    issue_stage(0, 0);  cp_commit();
    issue_stage(64, 1); cp_commit();
    cp_wait1();
    __syncthreads();

    for (int t = 0; t < ntiles; ++t) {
        const uint32_t* cAh = sm + (t & 1) * GSTG_U32;
        const uint32_t* cAl = cAh + GA_U32;
        const uint32_t* cBh = cAh + 2 * GA_U32;
        const uint32_t* cBl = cBh + GB_U32;

#pragma unroll
        for (int ks = 0; ks < 4; ++ks) {
            const int kb = ks * 8;
            uint32_t ah[4][4], al[4][4], bh[8][2], bl[8][2];
#pragma unroll
            for (int mt = 0; mt < 4; ++mt) {
                int r = wm * 64 + mt * 16 + g;
                int i0 = r * GAST + kb + tg;
                int i1 = (r + 8) * GAST + kb + tg;
                ah[mt][0] = cAh[i0];     ah[mt][1] = cAh[i1];
                ah[mt][2] = cAh[i0 + 4]; ah[mt][3] = cAh[i1 + 4];
                al[mt][0] = cAl[i0];     al[mt][1] = cAl[i1];
                al[mt][2] = cAl[i0 + 4]; al[mt][3] = cAl[i1 + 4];
            }
#pragma unroll
            for (int nt = 0; nt < 8; ++nt) {
                int n = wn * 64 + nt * 8 + g;
                int i0 = n * GAST + kb + tg;
                bh[nt][0] = cBh[i0]; bh[nt][1] = cBh[i0 + 4];
                bl[nt][0] = cBl[i0]; bl[nt][1] = cBl[i0 + 4];
            }
#pragma unroll
            for (int mt = 0; mt < 4; ++mt)
#pragma unroll
                for (int nt = 0; nt < 8; ++nt) {
                    mma16bf(acc[mt][nt], ah[mt], bh[nt]);  // hi*hi
                    mma16bf(acc[mt][nt], ah[mt], bl[nt]);  // hi*lo
                    mma16bf(acc[mt][nt], al[mt], bh[nt]);  // lo*hi
                }
        }

        __syncthreads();                     // everyone done with buf t&1
        if (t + 2 < ntiles) issue_stage((t + 2) * 64, t & 1);
        cp_commit();
        cp_wait1();                          // tile t+1 landed
        __syncthreads();
    }

#pragma unroll
    for (int mt = 0; mt < 4; ++mt)
#pragma unroll
        for (int nt = 0; nt < 8; ++nt) {
            int r = m0 + wm * 64 + mt * 16 + g;
            int c = n0 + wn * 64 + nt * 8 + tg * 2;
            *(float2*)(Cm + (size_t)r * N + c) =
                make_float2(acc[mt][nt][0], acc[mt][nt][1]);
            *(float2*)(Cm + (size_t)(r + 8) * N + c) =
                make_float2(acc[mt][nt][2], acc[mt][nt][3]);
        }
}

// ---------------------------------------------------------------------------
// RoPE, in-place on q and k halves of qkv.
// ---------------------------------------------------------------------------
__global__ void rope_kernel(float* __restrict__ qkv, const float* __restrict__ rope)
{
    int idx = blockIdx.x * blockDim.x + threadIdx.x;
    int d = idx & 63;
    int h = (idx >> 6) & 15;
    int m = idx >> 10;               // b*T + t
    int t = m & (Tt - 1);
    float cs = rope[(t * 64 + d) * 2 + 0];
    float sn = rope[(t * 64 + d) * 2 + 1];
    size_t base = (size_t)m * C3 + h * HDt + 2 * d;
    float2 q = *(float2*)(qkv + base);
    float2 k = *(float2*)(qkv + base + Ct);
    *(float2*)(qkv + base)      = make_float2(q.x * cs - q.y * sn, q.y * cs + q.x * sn);
    *(float2*)(qkv + base + Ct) = make_float2(k.x * cs - k.y * sn, k.y * cs + k.x * sn);
}

// ---------------------------------------------------------------------------
// Flash attention, tf32, causal. 1 block = (b, h, 128-row q tile). 256 thr,
// 8 warps x 16 rows. kv tile = 64. Q fragments in registers.
// ---------------------------------------------------------------------------
static constexpr int FLASH_SMEM_U32 = 64 * 132 + 64 * 132 + 128 * 68;
static constexpr int FLASH_SMEM = FLASH_SMEM_U32 * 4;  // 102400 B

__global__ __launch_bounds__(256, 1) void flash_kernel(
    const float* __restrict__ qkv,
    __nv_bfloat16* __restrict__ yh, __nv_bfloat16* __restrict__ yl)
{
    extern __shared__ uint32_t sm[];
    uint32_t* Ks = sm;                  // [64][132]
    uint32_t* Vs = Ks + 64 * 132;       // [64][132]
    uint32_t* Ps = Vs + 64 * 132;       // [128][68]

    const int tid = threadIdx.x;
    const int w = tid >> 5, lane = tid & 31;
    const int g = lane >> 2, tg = lane & 3;
    const int qt = (int)gridDim.x - 1 - (int)blockIdx.x;   // heavy tiles first
    const int bh = blockIdx.y;
    const int b = bh >> 4, h = bh & 15;
    const int q0 = qt * 128;
    const size_t rowbase = (size_t)(b * Tt) * C3;
    const int qcol = h * HDt, kcol = Ct + h * HDt;
    const int wr0 = w * 16;
    const float scale = 0.0883883476483184f;  // 1/sqrt(128)

    // Stage Q through Ks in two 64-row passes; pull fragments into registers.
    uint32_t qf[16][4];
#pragma unroll
    for (int pass = 0; pass < 2; ++pass) {
#pragma unroll
        for (int i = 0; i < 8; ++i) {
            int id = tid + i * 256;
            int r = id >> 5, c = (id & 31) * 4;
            float4 v = *(const float4*)(qkv + rowbase +
                        (size_t)(q0 + pass * 64 + r) * C3 + qcol + c);
            Ks[r * 132 + c + 0] = f2tf(v.x);
            Ks[r * 132 + c + 1] = f2tf(v.y);
            Ks[r * 132 + c + 2] = f2tf(v.z);
            Ks[r * 132 + c + 3] = f2tf(v.w);
        }
        __syncthreads();
        if ((w >> 2) == pass) {          // warps 0-3 take pass 0, 4-7 pass 1
            int rloc = (wr0 & 63) + g;
#pragma unroll
            for (int kk = 0; kk < 16; ++kk) {
                int ar = rloc * 132 + kk * 8 + tg;
                qf[kk][0] = Ks[ar];
                qf[kk][1] = Ks[ar + 8 * 132];
                qf[kk][2] = Ks[ar + 4];
                qf[kk][3] = Ks[ar + 8 * 132 + 4];
            }
        }
        __syncthreads();
    }

    float m_a = -1e30f, m_b = -1e30f, l_a = 0.f, l_b = 0.f;
    float o[16][4];
#pragma unroll
    for (int nt = 0; nt < 16; ++nt)
#pragma unroll
        for (int q = 0; q < 4; ++q) o[nt][q] = 0.f;

    const int njt = 2 * qt + 2;              // kv tiles of 64 rows
    for (int j = 0; j < njt; ++j) {
        const int kv0 = j * 64;
#pragma unroll 4
        for (int i = 0; i < 8; ++i) {
            int id = tid + i * 256;
            int r = id >> 5, c = (id & 31) * 4;
            const float* kp = qkv + rowbase + (size_t)(kv0 + r) * C3 + kcol + c;
            float4 kv4 = *(const float4*)kp;
            float4 vv4 = *(const float4*)(kp + Ct);
            Ks[r * 132 + c + 0] = f2tf(kv4.x);
            Ks[r * 132 + c + 1] = f2tf(kv4.y);
            Ks[r * 132 + c + 2] = f2tf(kv4.z);
            Ks[r * 132 + c + 3] = f2tf(kv4.w);
            Vs[r * 132 + c + 0] = f2tf(vv4.x);
            Vs[r * 132 + c + 1] = f2tf(vv4.y);
            Vs[r * 132 + c + 2] = f2tf(vv4.z);
            Vs[r * 132 + c + 3] = f2tf(vv4.w);
        }
        __syncthreads();

        // Warps whose rows are entirely in the past of this kv tile skip it.
        if (kv0 <= q0 + wr0 + 15) {
            float s[8][4];
#pragma unroll
            for (int nt = 0; nt < 8; ++nt)
#pragma unroll
                for (int q = 0; q < 4; ++q) s[nt][q] = 0.f;
#pragma unroll
            for (int kk = 0; kk < 16; ++kk) {
#pragma unroll
                for (int nt = 0; nt < 8; ++nt) {
                    uint32_t bb[2];
                    int br = (nt * 8 + g) * 132 + kk * 8 + tg;
                    bb[0] = Ks[br];
                    bb[1] = Ks[br + 4];
                    mma8(s[nt], qf[kk], bb);
                }
            }

#pragma unroll
            for (int nt = 0; nt < 8; ++nt)
#pragma unroll
                for (int q = 0; q < 4; ++q) s[nt][q] *= scale;

            if (kv0 + 63 > q0 + wr0) {       // diagonal crosses this warp's rows
                int ra = q0 + wr0 + g, rb = ra + 8;
#pragma unroll
                for (int nt = 0; nt < 8; ++nt) {
                    int c0 = kv0 + nt * 8 + tg * 2;
                    if (c0     > ra) s[nt][0] = -1e30f;
                    if (c0 + 1 > ra) s[nt][1] = -1e30f;
                    if (c0     > rb) s[nt][2] = -1e30f;
                    if (c0 + 1 > rb) s[nt][3] = -1e30f;
                }
            }

            // online softmax
            float tma = -1e30f, tmb = -1e30f;
#pragma unroll
            for (int nt = 0; nt < 8; ++nt) {
                tma = fmaxf(tma, fmaxf(s[nt][0], s[nt][1]));
                tmb = fmaxf(tmb, fmaxf(s[nt][2], s[nt][3]));
            }
            tma = fmaxf(tma, __shfl_xor_sync(0xffffffffu, tma, 1));
            tma = fmaxf(tma, __shfl_xor_sync(0xffffffffu, tma, 2));
            tmb = fmaxf(tmb, __shfl_xor_sync(0xffffffffu, tmb, 1));
            tmb = fmaxf(tmb, __shfl_xor_sync(0xffffffffu, tmb, 2));
            float mna = fmaxf(m_a, tma), mnb = fmaxf(m_b, tmb);
            float aa = __expf(m_a - mna), ab = __expf(m_b - mnb);
            float rsa = 0.f, rsb = 0.f;
#pragma unroll
            for (int nt = 0; nt < 8; ++nt) {
                s[nt][0] = __expf(s[nt][0] - mna);
                s[nt][1] = __expf(s[nt][1] - mna);
                s[nt][2] = __expf(s[nt][2] - mnb);
                s[nt][3] = __expf(s[nt][3] - mnb);
                rsa += s[nt][0] + s[nt][1];
                rsb += s[nt][2] + s[nt][3];
            }
            rsa += __shfl_xor_sync(0xffffffffu, rsa, 1);
            rsa += __shfl_xor_sync(0xffffffffu, rsa, 2);
            rsb += __shfl_xor_sync(0xffffffffu, rsb, 1);
            rsb += __shfl_xor_sync(0xffffffffu, rsb, 2);
            l_a = l_a * aa + rsa;
            l_b = l_b * ab + rsb;
            m_a = mna;
            m_b = mnb;
#pragma unroll
            for (int nt = 0; nt < 16; ++nt) {
                o[nt][0] *= aa; o[nt][1] *= aa;
                o[nt][2] *= ab; o[nt][3] *= ab;
            }

            // store P (tf32 bits) to per-warp smem region
#pragma unroll
            for (int nt = 0; nt < 8; ++nt) {
                int c0 = nt * 8 + tg * 2;
                Ps[(wr0 + g) * 68 + c0]     = f2tf(s[nt][0]);
                Ps[(wr0 + g) * 68 + c0 + 1] = f2tf(s[nt][1]);
                Ps[(wr0 + g + 8) * 68 + c0]     = f2tf(s[nt][2]);
                Ps[(wr0 + g + 8) * 68 + c0 + 1] = f2tf(s[nt][3]);
            }
            __syncwarp();

            // O += P @ V   (16x128 per warp)
#pragma unroll
            for (int kk = 0; kk < 8; ++kk) {
                uint32_t a[4];
                int ar = (wr0 + g) * 68 + kk * 8 + tg;
                a[0] = Ps[ar];
                a[1] = Ps[ar + 8 * 68];
                a[2] = Ps[ar + 4];
                a[3] = Ps[ar + 8 * 68 + 4];
#pragma unroll
                for (int nt = 0; nt < 16; ++nt) {
                    uint32_t bb[2];
                    int br = (kk * 8 + tg) * 132 + nt * 8 + g;
                    bb[0] = Vs[br];
                    bb[1] = Vs[br + 4 * 132];
                    mma8(o[nt], a, bb);
                }
            }
        }
        __syncthreads();     // all warps done reading Ks/Vs before next fill
    }

    // epilogue: normalize, write split-bf16 y (feeds GEMM2 directly)
    float inva = 1.f / l_a, invb = 1.f / l_b;
    int ra_tok = b * Tt + q0 + wr0 + g;
#pragma unroll
    for (int nt = 0; nt < 16; ++nt) {
        int c = h * HDt + nt * 8 + tg * 2;
        float va0 = o[nt][0] * inva, va1 = o[nt][1] * inva;
        float vb0 = o[nt][2] * invb, vb1 = o[nt][3] * invb;
        __nv_bfloat16 h0, l0, h1, l1;
        split_bf16(va0, h0, l0); split_bf16(va1, h1, l1);
        *(__nv_bfloat162*)(yh + (size_t)ra_tok * Ct + c) = __nv_bfloat162(h0, h1);
        *(__nv_bfloat162*)(yl + (size_t)ra_tok * Ct + c) = __nv_bfloat162(l0, l1);
        split_bf16(vb0, h0, l0); split_bf16(vb1, h1, l1);
        *(__nv_bfloat162*)(yh + (size_t)(ra_tok + 8) * Ct + c) = __nv_bfloat162(h0, h1);
        *(__nv_bfloat162*)(yl + (size_t)(ra_tok + 8) * Ct + c) = __nv_bfloat162(l0, l1);
    }
}

// ---------------------------------------------------------------------------
extern "C" void kernel_launch(void* const* d_in, const int* in_sizes, int n_in,
                              void* d_out, int out_size)
{
    const float* x     = (const float*)d_in[0];
    const float* rope  = (const float*)d_in[1];
    const float* Wqkv  = (const float*)d_in[2];
    const float* Wproj = (const float*)d_in[3];
    float* out = (float*)d_out;

    float* qkv;
    __nv_bfloat16 *xh, *xl, *wqh, *wql, *wph, *wpl, *yh, *yl;
    cudaGetSymbolAddress((void**)&qkv, g_qkv);
    cudaGetSymbolAddress((void**)&xh, g_xh);
    cudaGetSymbolAddress((void**)&xl, g_xl);
    cudaGetSymbolAddress((void**)&wqh, g_wqh);
    cudaGetSymbolAddress((void**)&wql, g_wql);
    cudaGetSymbolAddress((void**)&wph, g_wph);
    cudaGetSymbolAddress((void**)&wpl, g_wpl);
    cudaGetSymbolAddress((void**)&yh, g_yh);
    cudaGetSymbolAddress((void**)&yl, g_yl);

    cudaFuncSetAttribute(gemm_bf16x2, cudaFuncAttributeMaxDynamicSharedMemorySize,
                         GEMM_SMEM);
    cudaFuncSetAttribute(flash_kernel, cudaFuncAttributeMaxDynamicSharedMemorySize,
                         FLASH_SMEM);

    // 0) split/transpose pre-pass
    {
        size_t nx = (size_t)MTOT * Ct;
        split_rows_kernel<<<(unsigned)((nx + 255) / 256), 256>>>(x, xh, xl, nx);
        split_transpose_kernel<<<dim3(C3 / 32, Ct / 32), dim3(32, 8)>>>(Wqkv, wqh, wql, Ct, C3);
        split_transpose_kernel<<<dim3(Ct / 32, Ct / 32), dim3(32, 8)>>>(Wproj, wph, wpl, Ct, Ct);
    }

    // 1) qkv = x @ Wqkv   (M=8192, N=6144, K=2048)
    gemm_bf16x2<<<dim3(C3 / 256, MTOT / 128), 256, GEMM_SMEM>>>(
        xh, xl, wqh, wql, qkv, MTOT, C3, Ct);

    // 2) RoPE in-place on q, k
    rope_kernel<<<(MTOT * Ht * (HDt / 2)) / 256, 256>>>(qkv, rope);

    // 3) flash attention -> y (split bf16)
    flash_kernel<<<dim3(Tt / 128, Bt * Ht), 256, FLASH_SMEM>>>(qkv, yh, yl);

    // 4) out = y @ Wproj  (M=8192, N=2048, K=2048)
    gemm_bf16x2<<<dim3(Ct / 256, MTOT / 128), 256, GEMM_SMEM>>>(
        yh, yl, wph, wpl, out, MTOT, Ct, Ct);
}

// round 6
// speedup vs baseline: 2.4245x; 1.0045x over previous
#include <cuda_runtime.h>
#include <cuda_bf16.h>
#include <cstdint>

// ---------------------------------------------------------------------------
// CasualSelfAttention: B=4, T=2048, C=2048, H=16, HD=128
//   qkv = x @ Wqkv (+fused RoPE) ; flash-attention (causal) ; out = y @ Wproj
// GEMMs: split-bf16 (hi+lo, 3x mma.m16n8k16) pass-major MMA order,
//        cp.async double-buffered, CTA tile 128x256, warp tile 64x64, K=64.
// Attention: tf32 flash kernel, 128 q-rows/CTA (8 warps), Q in registers.
// ---------------------------------------------------------------------------

#define DEVINLINE __device__ __forceinline__

static constexpr int Bt = 4;
static constexpr int Tt = 2048;
static constexpr int Ct = 2048;
static constexpr int Ht = 16;
static constexpr int HDt = 128;
static constexpr int MTOT = Bt * Tt;        // 8192
static constexpr int C3 = 3 * Ct;           // 6144

// Scratch (device globals: allocation-free rule)
__device__ float g_qkv[(size_t)MTOT * C3];            // 201 MB
__device__ __nv_bfloat16 g_xh[(size_t)MTOT * Ct];
__device__ __nv_bfloat16 g_xl[(size_t)MTOT * Ct];
__device__ __nv_bfloat16 g_wqh[(size_t)C3 * Ct];      // transposed [N][K]
__device__ __nv_bfloat16 g_wql[(size_t)C3 * Ct];
__device__ __nv_bfloat16 g_wph[(size_t)Ct * Ct];      // transposed [N][K]
__device__ __nv_bfloat16 g_wpl[(size_t)Ct * Ct];
__device__ __nv_bfloat16 g_yh[(size_t)MTOT * Ct];
__device__ __nv_bfloat16 g_yl[(size_t)MTOT * Ct];

DEVINLINE uint32_t f2tf(float f) {
    uint32_t u;
    asm("cvt.rna.tf32.f32 %0, %1;" : "=r"(u) : "f"(f));
    return u;
}

DEVINLINE void mma8(float* d, const uint32_t* a, const uint32_t* b) {
    asm volatile(
        "mma.sync.aligned.m16n8k8.row.col.f32.tf32.tf32.f32 "
        "{%0,%1,%2,%3}, {%4,%5,%6,%7}, {%8,%9}, {%0,%1,%2,%3};"
        : "+f"(d[0]), "+f"(d[1]), "+f"(d[2]), "+f"(d[3])
        : "r"(a[0]), "r"(a[1]), "r"(a[2]), "r"(a[3]), "r"(b[0]), "r"(b[1]));
}

DEVINLINE void mma16bf(float* d, const uint32_t* a, const uint32_t* b) {
    asm volatile(
        "mma.sync.aligned.m16n8k16.row.col.f32.bf16.bf16.f32 "
        "{%0,%1,%2,%3}, {%4,%5,%6,%7}, {%8,%9}, {%0,%1,%2,%3};"
        : "+f"(d[0]), "+f"(d[1]), "+f"(d[2]), "+f"(d[3])
        : "r"(a[0]), "r"(a[1]), "r"(a[2]), "r"(a[3]), "r"(b[0]), "r"(b[1]));
}

DEVINLINE void cpasync16(uint32_t saddr, const void* g) {
    asm volatile("cp.async.cg.shared.global [%0], [%1], 16;\n"
                 :: "r"(saddr), "l"(g));
}
DEVINLINE void cp_commit() { asm volatile("cp.async.commit_group;\n"); }
DEVINLINE void cp_wait1()  { asm volatile("cp.async.wait_group 1;\n" ::: "memory"); }

DEVINLINE void split_bf16(float v, __nv_bfloat16& hi, __nv_bfloat16& lo) {
    hi = __float2bfloat16(v);
    lo = __float2bfloat16(v - __bfloat162float(hi));
}

// ---------------------------------------------------------------------------
// Pre-pass kernels
// ---------------------------------------------------------------------------
__global__ void split_rows_kernel(const float* __restrict__ src,
                                  __nv_bfloat16* __restrict__ dh,
                                  __nv_bfloat16* __restrict__ dl, size_t n)
{
    size_t i = (size_t)blockIdx.x * blockDim.x + threadIdx.x;
    if (i >= n) return;
    __nv_bfloat16 h, l;
    split_bf16(src[i], h, l);
    dh[i] = h; dl[i] = l;
}

__global__ void split_transpose_kernel(const float* __restrict__ W,
                                       __nv_bfloat16* __restrict__ th,
                                       __nv_bfloat16* __restrict__ tl,
                                       int K, int N)
{
    __shared__ float tile[32][33];
    int nx = blockIdx.x * 32, ky = blockIdx.y * 32;
    int tx = threadIdx.x, ty = threadIdx.y;   // 32 x 8
#pragma unroll
    for (int s = 0; s < 4; ++s)
        tile[ty + 8 * s][tx] = W[(size_t)(ky + ty + 8 * s) * N + nx + tx];
    __syncthreads();
#pragma unroll
    for (int s = 0; s < 4; ++s) {
        float v = tile[tx][ty + 8 * s];
        __nv_bfloat16 h, l;
        split_bf16(v, h, l);
        size_t idx = (size_t)(nx + ty + 8 * s) * K + ky + tx;
        th[idx] = h; tl[idx] = l;
    }
}

// ---------------------------------------------------------------------------
// Split-bf16 GEMM: C[M,N] = A[M,K] @ B^T (B given as [N][K]).
// CTA tile 128x256, 8 warps (2x4), warp tile 64x64, K-tile 64.
// Pass-major MMA order (3 sweeps over 32 independent accumulators).
// Optional fused RoPE epilogue (ropep != nullptr, N == 6144 layout).
// ---------------------------------------------------------------------------
static constexpr int GAST = 36;                      // u32 row stride
static constexpr int GA_U32 = 128 * GAST;            // 4608 per A array
static constexpr int GB_U32 = 256 * GAST;            // 9216 per B array
static constexpr int GSTG_U32 = 2 * GA_U32 + 2 * GB_U32;  // 27648 per stage
static constexpr int GEMM_SMEM = 2 * GSTG_U32 * 4;   // 221184 B

__global__ __launch_bounds__(256, 1) void gemm_bf16x2(
    const __nv_bfloat16* __restrict__ Ah, const __nv_bfloat16* __restrict__ Al,
    const __nv_bfloat16* __restrict__ Bh, const __nv_bfloat16* __restrict__ Bl,
    float* __restrict__ Cm, int M, int N, int K,
    const float* __restrict__ ropep)
{
    extern __shared__ uint32_t sm[];

    const int tid = threadIdx.x;
    const int w = tid >> 5, lane = tid & 31;
    const int wm = w >> 2, wn = w & 3;          // 2 x 4 warps
    const int g = lane >> 2, tg = lane & 3;
    const int m0 = blockIdx.y * 128, n0 = blockIdx.x * 256;

    const uint32_t sbase = (uint32_t)__cvta_generic_to_shared(sm);

    auto issue_stage = [&](int kt, int s) {
        const uint32_t st = sbase + (uint32_t)s * GSTG_U32 * 4;
        const uint32_t stAh = st;
        const uint32_t stAl = st + GA_U32 * 4;
        const uint32_t stBh = st + 2 * GA_U32 * 4;
        const uint32_t stBl = st + 2 * GA_U32 * 4 + GB_U32 * 4;
#pragma unroll
        for (int i = 0; i < 4; ++i) {            // A: 1024 16B-chunks
            int id = tid + i * 256;
            int r = id >> 3, c = id & 7;
            uint32_t d = (uint32_t)r * (GAST * 4) + c * 16;
            size_t ga = (size_t)(m0 + r) * K + kt + c * 8;
            cpasync16(stAh + d, Ah + ga);
            cpasync16(stAl + d, Al + ga);
        }
#pragma unroll
        for (int i = 0; i < 8; ++i) {            // B: 2048 16B-chunks
            int id = tid + i * 256;
            int r = id >> 3, c = id & 7;
            uint32_t d = (uint32_t)r * (GAST * 4) + c * 16;
            size_t gb = (size_t)(n0 + r) * K + kt + c * 8;
            cpasync16(stBh + d, Bh + gb);
            cpasync16(stBl + d, Bl + gb);
        }
    };

    float acc[4][8][4];
#pragma unroll
    for (int mt = 0; mt < 4; ++mt)
#pragma unroll
        for (int nt = 0; nt < 8; ++nt)
#pragma unroll
            for (int q = 0; q < 4; ++q) acc[mt][nt][q] = 0.f;

    const int ntiles = K / 64;
    issue_stage(0, 0);  cp_commit();
    issue_stage(64, 1); cp_commit();
    cp_wait1();
    __syncthreads();

    for (int t = 0; t < ntiles; ++t) {
        const uint32_t* cAh = sm + (t & 1) * GSTG_U32;
        const uint32_t* cAl = cAh + GA_U32;
        const uint32_t* cBh = cAh + 2 * GA_U32;
        const uint32_t* cBl = cBh + GB_U32;

#pragma unroll
        for (int ks = 0; ks < 4; ++ks) {
            const int kb = ks * 8;
            uint32_t ah[4][4], al[4][4], bh[8][2], bl[8][2];
#pragma unroll
            for (int mt = 0; mt < 4; ++mt) {
                int r = wm * 64 + mt * 16 + g;
                int i0 = r * GAST + kb + tg;
                int i1 = (r + 8) * GAST + kb + tg;
                ah[mt][0] = cAh[i0];     ah[mt][1] = cAh[i1];
                ah[mt][2] = cAh[i0 + 4]; ah[mt][3] = cAh[i1 + 4];
                al[mt][0] = cAl[i0];     al[mt][1] = cAl[i1];
                al[mt][2] = cAl[i0 + 4]; al[mt][3] = cAl[i1 + 4];
            }
#pragma unroll
            for (int nt = 0; nt < 8; ++nt) {
                int n = wn * 64 + nt * 8 + g;
                int i0 = n * GAST + kb + tg;
                bh[nt][0] = cBh[i0]; bh[nt][1] = cBh[i0 + 4];
                bl[nt][0] = cBl[i0]; bl[nt][1] = cBl[i0 + 4];
            }
            // Pass-major: 3 sweeps of 32 independent accumulators each.
            // Per-acc addition order (HH, HL, LH) identical to the fused form.
#pragma unroll
            for (int mt = 0; mt < 4; ++mt)
#pragma unroll
                for (int nt = 0; nt < 8; ++nt)
                    mma16bf(acc[mt][nt], ah[mt], bh[nt]);   // hi*hi
#pragma unroll
            for (int mt = 0; mt < 4; ++mt)
#pragma unroll
                for (int nt = 0; nt < 8; ++nt)
                    mma16bf(acc[mt][nt], ah[mt], bl[nt]);   // hi*lo
#pragma unroll
            for (int mt = 0; mt < 4; ++mt)
#pragma unroll
                for (int nt = 0; nt < 8; ++nt)
                    mma16bf(acc[mt][nt], al[mt], bh[nt]);   // lo*hi
        }

        __syncthreads();                     // everyone done with buf t&1
        if (t + 2 < ntiles) issue_stage((t + 2) * 64, t & 1);
        cp_commit();
        cp_wait1();                          // tile t+1 landed
        __syncthreads();
    }

    // Epilogue; optional fused RoPE (pair = this thread's float2).
#pragma unroll
    for (int mt = 0; mt < 4; ++mt)
#pragma unroll
        for (int nt = 0; nt < 8; ++nt) {
            int r = m0 + wm * 64 + mt * 16 + g;
            int c = n0 + wn * 64 + nt * 8 + tg * 2;
            float2 v0 = make_float2(acc[mt][nt][0], acc[mt][nt][1]);
            float2 v1 = make_float2(acc[mt][nt][2], acc[mt][nt][3]);
            if (ropep != nullptr && c < 2 * Ct) {
                int d = (c & (HDt - 1)) >> 1;
                int t0 = r & (Tt - 1);
                float2 cs0 = *(const float2*)(ropep + (size_t)(t0 * 64 + d) * 2);
                float2 cs1 = *(const float2*)(ropep + (size_t)(((r + 8) & (Tt - 1)) * 64 + d) * 2);
                v0 = make_float2(v0.x * cs0.x - v0.y * cs0.y,
                                 v0.y * cs0.x + v0.x * cs0.y);
                v1 = make_float2(v1.x * cs1.x - v1.y * cs1.y,
                                 v1.y * cs1.x + v1.x * cs1.y);
            }
            *(float2*)(Cm + (size_t)r * N + c) = v0;
            *(float2*)(Cm + (size_t)(r + 8) * N + c) = v1;
        }
}

// ---------------------------------------------------------------------------
// Flash attention, tf32, causal. 1 block = (b, h, 128-row q tile). 256 thr,
// 8 warps x 16 rows. kv tile = 64. Q fragments in registers.
// ---------------------------------------------------------------------------
static constexpr int FLASH_SMEM_U32 = 64 * 132 + 64 * 132 + 128 * 68;
static constexpr int FLASH_SMEM = FLASH_SMEM_U32 * 4;  // 102400 B

__global__ __launch_bounds__(256, 1) void flash_kernel(
    const float* __restrict__ qkv,
    __nv_bfloat16* __restrict__ yh, __nv_bfloat16* __restrict__ yl)
{
    extern __shared__ uint32_t sm[];
    uint32_t* Ks = sm;                  // [64][132]
    uint32_t* Vs = Ks + 64 * 132;       // [64][132]
    uint32_t* Ps = Vs + 64 * 132;       // [128][68]

    const int tid = threadIdx.x;
    const int w = tid >> 5, lane = tid & 31;
    const int g = lane >> 2, tg = lane & 3;
    const int qt = (int)gridDim.x - 1 - (int)blockIdx.x;   // heavy tiles first
    const int bh = blockIdx.y;
    const int b = bh >> 4, h = bh & 15;
    const int q0 = qt * 128;
    const size_t rowbase = (size_t)(b * Tt) * C3;
    const int qcol = h * HDt, kcol = Ct + h * HDt;
    const int wr0 = w * 16;
    const float scale = 0.0883883476483184f;  // 1/sqrt(128)

    // Stage Q through Ks in two 64-row passes; pull fragments into registers.
    uint32_t qf[16][4];
#pragma unroll
    for (int pass = 0; pass < 2; ++pass) {
#pragma unroll
        for (int i = 0; i < 8; ++i) {
            int id = tid + i * 256;
            int r = id >> 5, c = (id & 31) * 4;
            float4 v = *(const float4*)(qkv + rowbase +
                        (size_t)(q0 + pass * 64 + r) * C3 + qcol + c);
            Ks[r * 132 + c + 0] = f2tf(v.x);
            Ks[r * 132 + c + 1] = f2tf(v.y);
            Ks[r * 132 + c + 2] = f2tf(v.z);
            Ks[r * 132 + c + 3] = f2tf(v.w);
        }
        __syncthreads();
        if ((w >> 2) == pass) {          // warps 0-3 take pass 0, 4-7 pass 1
            int rloc = (wr0 & 63) + g;
#pragma unroll
            for (int kk = 0; kk < 16; ++kk) {
                int ar = rloc * 132 + kk * 8 + tg;
                qf[kk][0] = Ks[ar];
                qf[kk][1] = Ks[ar + 8 * 132];
                qf[kk][2] = Ks[ar + 4];
                qf[kk][3] = Ks[ar + 8 * 132 + 4];
            }
        }
        __syncthreads();
    }

    float m_a = -1e30f, m_b = -1e30f, l_a = 0.f, l_b = 0.f;
    float o[16][4];
#pragma unroll
    for (int nt = 0; nt < 16; ++nt)
#pragma unroll
        for (int q = 0; q < 4; ++q) o[nt][q] = 0.f;

    const int njt = 2 * qt + 2;              // kv tiles of 64 rows
    for (int j = 0; j < njt; ++j) {
        const int kv0 = j * 64;
#pragma unroll 4
        for (int i = 0; i < 8; ++i) {
            int id = tid + i * 256;
            int r = id >> 5, c = (id & 31) * 4;
            const float* kp = qkv + rowbase + (size_t)(kv0 + r) * C3 + kcol + c;
            float4 kv4 = *(const float4*)kp;
            float4 vv4 = *(const float4*)(kp + Ct);
            Ks[r * 132 + c + 0] = f2tf(kv4.x);
            Ks[r * 132 + c + 1] = f2tf(kv4.y);
            Ks[r * 132 + c + 2] = f2tf(kv4.z);
            Ks[r * 132 + c + 3] = f2tf(kv4.w);
            Vs[r * 132 + c + 0] = f2tf(vv4.x);
            Vs[r * 132 + c + 1] = f2tf(vv4.y);
            Vs[r * 132 + c + 2] = f2tf(vv4.z);
            Vs[r * 132 + c + 3] = f2tf(vv4.w);
        }
        __syncthreads();

        // Warps whose rows are entirely in the past of this kv tile skip it.
        if (kv0 <= q0 + wr0 + 15) {
            float s[8][4];
#pragma unroll
            for (int nt = 0; nt < 8; ++nt)
#pragma unroll
                for (int q = 0; q < 4; ++q) s[nt][q] = 0.f;
#pragma unroll
            for (int kk = 0; kk < 16; ++kk) {
#pragma unroll
                for (int nt = 0; nt < 8; ++nt) {
                    uint32_t bb[2];
                    int br = (nt * 8 + g) * 132 + kk * 8 + tg;
                    bb[0] = Ks[br];
                    bb[1] = Ks[br + 4];
                    mma8(s[nt], qf[kk], bb);
                }
            }

#pragma unroll
            for (int nt = 0; nt < 8; ++nt)
#pragma unroll
                for (int q = 0; q < 4; ++q) s[nt][q] *= scale;

            if (kv0 + 63 > q0 + wr0) {       // diagonal crosses this warp's rows
                int ra = q0 + wr0 + g, rb = ra + 8;
#pragma unroll
                for (int nt = 0; nt < 8; ++nt) {
                    int c0 = kv0 + nt * 8 + tg * 2;
                    if (c0     > ra) s[nt][0] = -1e30f;
                    if (c0 + 1 > ra) s[nt][1] = -1e30f;
                    if (c0     > rb) s[nt][2] = -1e30f;
                    if (c0 + 1 > rb) s[nt][3] = -1e30f;
                }
            }

            // online softmax
            float tma = -1e30f, tmb = -1e30f;
#pragma unroll
            for (int nt = 0; nt < 8; ++nt) {
                tma = fmaxf(tma, fmaxf(s[nt][0], s[nt][1]));
                tmb = fmaxf(tmb, fmaxf(s[nt][2], s[nt][3]));
            }
            tma = fmaxf(tma, __shfl_xor_sync(0xffffffffu, tma, 1));
            tma = fmaxf(tma, __shfl_xor_sync(0xffffffffu, tma, 2));
            tmb = fmaxf(tmb, __shfl_xor_sync(0xffffffffu, tmb, 1));
            tmb = fmaxf(tmb, __shfl_xor_sync(0xffffffffu, tmb, 2));
            float mna = fmaxf(m_a, tma), mnb = fmaxf(m_b, tmb);
            float aa = __expf(m_a - mna), ab = __expf(m_b - mnb);
            float rsa = 0.f, rsb = 0.f;
#pragma unroll
            for (int nt = 0; nt < 8; ++nt) {
                s[nt][0] = __expf(s[nt][0] - mna);
                s[nt][1] = __expf(s[nt][1] - mna);
                s[nt][2] = __expf(s[nt][2] - mnb);
                s[nt][3] = __expf(s[nt][3] - mnb);
                rsa += s[nt][0] + s[nt][1];
                rsb += s[nt][2] + s[nt][3];
            }
            rsa += __shfl_xor_sync(0xffffffffu, rsa, 1);
            rsa += __shfl_xor_sync(0xffffffffu, rsa, 2);
            rsb += __shfl_xor_sync(0xffffffffu, rsb, 1);
            rsb += __shfl_xor_sync(0xffffffffu, rsb, 2);
            l_a = l_a * aa + rsa;
            l_b = l_b * ab + rsb;
            m_a = mna;
            m_b = mnb;
#pragma unroll
            for (int nt = 0; nt < 16; ++nt) {
                o[nt][0] *= aa; o[nt][1] *= aa;
                o[nt][2] *= ab; o[nt][3] *= ab;
            }

            // store P (tf32 bits) to per-warp smem region
#pragma unroll
            for (int nt = 0; nt < 8; ++nt) {
                int c0 = nt * 8 + tg * 2;
                Ps[(wr0 + g) * 68 + c0]     = f2tf(s[nt][0]);
                Ps[(wr0 + g) * 68 + c0 + 1] = f2tf(s[nt][1]);
                Ps[(wr0 + g + 8) * 68 + c0]     = f2tf(s[nt][2]);
                Ps[(wr0 + g + 8) * 68 + c0 + 1] = f2tf(s[nt][3]);
            }
            __syncwarp();

            // O += P @ V   (16x128 per warp)
#pragma unroll
            for (int kk = 0; kk < 8; ++kk) {
                uint32_t a[4];
                int ar = (wr0 + g) * 68 + kk * 8 + tg;
                a[0] = Ps[ar];
                a[1] = Ps[ar + 8 * 68];
                a[2] = Ps[ar + 4];
                a[3] = Ps[ar + 8 * 68 + 4];
#pragma unroll
                for (int nt = 0; nt < 16; ++nt) {
                    uint32_t bb[2];
                    int br = (kk * 8 + tg) * 132 + nt * 8 + g;
                    bb[0] = Vs[br];
                    bb[1] = Vs[br + 4 * 132];
                    mma8(o[nt], a, bb);
                }
            }
        }
        __syncthreads();     // all warps done reading Ks/Vs before next fill
    }

    // epilogue: normalize, write split-bf16 y (feeds GEMM2 directly)
    float inva = 1.f / l_a, invb = 1.f / l_b;
    int ra_tok = b * Tt + q0 + wr0 + g;
#pragma unroll
    for (int nt = 0; nt < 16; ++nt) {
        int c = h * HDt + nt * 8 + tg * 2;
        float va0 = o[nt][0] * inva, va1 = o[nt][1] * inva;
        float vb0 = o[nt][2] * invb, vb1 = o[nt][3] * invb;
        __nv_bfloat16 h0, l0, h1, l1;
        split_bf16(va0, h0, l0); split_bf16(va1, h1, l1);
        *(__nv_bfloat162*)(yh + (size_t)ra_tok * Ct + c) = __nv_bfloat162(h0, h1);
        *(__nv_bfloat162*)(yl + (size_t)ra_tok * Ct + c) = __nv_bfloat162(l0, l1);
        split_bf16(vb0, h0, l0); split_bf16(vb1, h1, l1);
        *(__nv_bfloat162*)(yh + (size_t)(ra_tok + 8) * Ct + c) = __nv_bfloat162(h0, h1);
        *(__nv_bfloat162*)(yl + (size_t)(ra_tok + 8) * Ct + c) = __nv_bfloat162(l0, l1);
    }
}

// ---------------------------------------------------------------------------
extern "C" void kernel_launch(void* const* d_in, const int* in_sizes, int n_in,
                              void* d_out, int out_size)
{
    const float* x     = (const float*)d_in[0];
    const float* rope  = (const float*)d_in[1];
    const float* Wqkv  = (const float*)d_in[2];
    const float* Wproj = (const float*)d_in[3];
    float* out = (float*)d_out;

    float* qkv;
    __nv_bfloat16 *xh, *xl, *wqh, *wql, *wph, *wpl, *yh, *yl;
    cudaGetSymbolAddress((void**)&qkv, g_qkv);
    cudaGetSymbolAddress((void**)&xh, g_xh);
    cudaGetSymbolAddress((void**)&xl, g_xl);
    cudaGetSymbolAddress((void**)&wqh, g_wqh);
    cudaGetSymbolAddress((void**)&wql, g_wql);
    cudaGetSymbolAddress((void**)&wph, g_wph);
    cudaGetSymbolAddress((void**)&wpl, g_wpl);
    cudaGetSymbolAddress((void**)&yh, g_yh);
    cudaGetSymbolAddress((void**)&yl, g_yl);

    cudaFuncSetAttribute(gemm_bf16x2, cudaFuncAttributeMaxDynamicSharedMemorySize,
                         GEMM_SMEM);
    cudaFuncSetAttribute(flash_kernel, cudaFuncAttributeMaxDynamicSharedMemorySize,
                         FLASH_SMEM);

    // 0) split/transpose pre-pass
    {
        size_t nx = (size_t)MTOT * Ct;
        split_rows_kernel<<<(unsigned)((nx + 255) / 256), 256>>>(x, xh, xl, nx);
        split_transpose_kernel<<<dim3(C3 / 32, Ct / 32), dim3(32, 8)>>>(Wqkv, wqh, wql, Ct, C3);
        split_transpose_kernel<<<dim3(Ct / 32, Ct / 32), dim3(32, 8)>>>(Wproj, wph, wpl, Ct, Ct);
    }

    // 1) qkv = x @ Wqkv + fused RoPE  (M=8192, N=6144, K=2048)
    gemm_bf16x2<<<dim3(C3 / 256, MTOT / 128), 256, GEMM_SMEM>>>(
        xh, xl, wqh, wql, qkv, MTOT, C3, Ct, rope);

    // 2) flash attention -> y (split bf16)
    flash_kernel<<<dim3(Tt / 128, Bt * Ht), 256, FLASH_SMEM>>>(qkv, yh, yl);

    // 3) out = y @ Wproj  (M=8192, N=2048, K=2048)
    gemm_bf16x2<<<dim3(Ct / 256, MTOT / 128), 256, GEMM_SMEM>>>(
        yh, yl, wph, wpl, out, MTOT, Ct, Ct, nullptr);
}

// round 7
// speedup vs baseline: 3.8234x; 1.5770x over previous
#include <cuda_runtime.h>
#include <cuda_fp16.h>
#include <cstdint>

// ---------------------------------------------------------------------------
// CasualSelfAttention: B=4, T=2048, C=2048, H=16, HD=128
//   qkv = x @ Wqkv (+fused RoPE, fp16 out) ; flash-attn (fp16 mma, causal) ;
//   out = y @ Wproj
// GEMMs: fp16 2-term split (x_hi*(W_hi+W_lo)), mma.m16n8k16.f16,
//        cp.async double-buffered, CTA 128x256, warp 64x64, K-tile 64.
// Flash: fp16 m16n8k16, P in registers, V via ldmatrix.trans,
//        cp.async double-buffered K/V tiles.
// ---------------------------------------------------------------------------

#define DEVINLINE __device__ __forceinline__

static constexpr int Bt = 4;
static constexpr int Tt = 2048;
static constexpr int Ct = 2048;
static constexpr int Ht = 16;
static constexpr int HDt = 128;
static constexpr int MTOT = Bt * Tt;        // 8192
static constexpr int C3 = 3 * Ct;           // 6144

// Scratch (device globals: allocation-free rule)
__device__ __half g_qkv[(size_t)MTOT * C3];           // 100 MB (fp16)
__device__ __half g_xh[(size_t)MTOT * Ct];
__device__ __half g_wqh[(size_t)C3 * Ct];             // transposed [N][K]
__device__ __half g_wql[(size_t)C3 * Ct];
__device__ __half g_wph[(size_t)Ct * Ct];             // transposed [N][K]
__device__ __half g_wpl[(size_t)Ct * Ct];
__device__ __half g_y[(size_t)MTOT * Ct];

DEVINLINE void mma16f(float* d, const uint32_t* a, const uint32_t* b) {
    asm volatile(
        "mma.sync.aligned.m16n8k16.row.col.f32.f16.f16.f32 "
        "{%0,%1,%2,%3}, {%4,%5,%6,%7}, {%8,%9}, {%0,%1,%2,%3};"
        : "+f"(d[0]), "+f"(d[1]), "+f"(d[2]), "+f"(d[3])
        : "r"(a[0]), "r"(a[1]), "r"(a[2]), "r"(a[3]), "r"(b[0]), "r"(b[1]));
}

DEVINLINE void ldsm_x2_t(uint32_t& r0, uint32_t& r1, uint32_t addr) {
    asm volatile("ldmatrix.sync.aligned.m8n8.x2.trans.shared.b16 {%0,%1}, [%2];"
                 : "=r"(r0), "=r"(r1) : "r"(addr));
}

DEVINLINE void cpasync16(uint32_t saddr, const void* g) {
    asm volatile("cp.async.cg.shared.global [%0], [%1], 16;\n"
                 :: "r"(saddr), "l"(g));
}
DEVINLINE void cp_commit() { asm volatile("cp.async.commit_group;\n"); }
DEVINLINE void cp_wait1()  { asm volatile("cp.async.wait_group 1;\n" ::: "memory"); }
DEVINLINE void cp_wait0()  { asm volatile("cp.async.wait_group 0;\n" ::: "memory"); }

DEVINLINE uint32_t packh2(float x, float y) {
    __half2 h = __floats2half2_rn(x, y);
    return *(uint32_t*)&h;
}

// ---------------------------------------------------------------------------
// Pre-pass kernels
// ---------------------------------------------------------------------------
__global__ void tohalf_kernel(const float* __restrict__ src,
                              __half* __restrict__ dst, size_t n)
{
    size_t i = (size_t)blockIdx.x * blockDim.x + threadIdx.x;
    if (i < n) dst[i] = __float2half(src[i]);
}

// W[K][N] fp32 -> (hi, lo) fp16, transposed to [N][K]
__global__ void split_transpose_kernel(const float* __restrict__ W,
                                       __half* __restrict__ th,
                                       __half* __restrict__ tl,
                                       int K, int N)
{
    __shared__ float tile[32][33];
    int nx = blockIdx.x * 32, ky = blockIdx.y * 32;
    int tx = threadIdx.x, ty = threadIdx.y;   // 32 x 8
#pragma unroll
    for (int s = 0; s < 4; ++s)
        tile[ty + 8 * s][tx] = W[(size_t)(ky + ty + 8 * s) * N + nx + tx];
    __syncthreads();
#pragma unroll
    for (int s = 0; s < 4; ++s) {
        float v = tile[tx][ty + 8 * s];
        __half h = __float2half(v);
        __half l = __float2half(v - __half2float(h));
        size_t idx = (size_t)(nx + ty + 8 * s) * K + ky + tx;
        th[idx] = h; tl[idx] = l;
    }
}

// ---------------------------------------------------------------------------
// fp16 2-term GEMM: C[M,N] = A[M,K] @ (Bh+Bl)^T  (B arrays are [N][K]).
// CTA tile 128x256, 8 warps (2x4), warp tile 64x64, K-tile 64, 2-stage.
// ropep != nullptr: fused RoPE on cols < 2*Ct, fp16 output (qkv).
// ropep == nullptr: fp32 output.
// ---------------------------------------------------------------------------
static constexpr int GAST = 36;                      // u32 row stride (32 data + 4)
static constexpr int GA_U32 = 128 * GAST;            // 4608
static constexpr int GB_U32 = 256 * GAST;            // 9216
static constexpr int GSTG_U32 = GA_U32 + 2 * GB_U32; // 23040 per stage
static constexpr int GEMM_SMEM = 2 * GSTG_U32 * 4;   // 184320 B

__global__ __launch_bounds__(256, 1) void gemm_fp16x2(
    const __half* __restrict__ Ah,
    const __half* __restrict__ Bh, const __half* __restrict__ Bl,
    void* __restrict__ Cout, int M, int N, int K,
    const float* __restrict__ ropep)
{
    extern __shared__ uint32_t sm[];

    const int tid = threadIdx.x;
    const int w = tid >> 5, lane = tid & 31;
    const int wm = w >> 2, wn = w & 3;          // 2 x 4 warps
    const int g = lane >> 2, tg = lane & 3;
    const int m0 = blockIdx.y * 128, n0 = blockIdx.x * 256;

    const uint32_t sbase = (uint32_t)__cvta_generic_to_shared(sm);

    auto issue_stage = [&](int kt, int s) {
        const uint32_t st = sbase + (uint32_t)s * GSTG_U32 * 4;
        const uint32_t stA  = st;
        const uint32_t stBh = st + GA_U32 * 4;
        const uint32_t stBl = st + GA_U32 * 4 + GB_U32 * 4;
#pragma unroll
        for (int i = 0; i < 4; ++i) {            // A: 1024 16B-chunks
            int id = tid + i * 256;
            int r = id >> 3, c = id & 7;
            uint32_t d = (uint32_t)r * (GAST * 4) + c * 16;
            cpasync16(stA + d, Ah + (size_t)(m0 + r) * K + kt + c * 8);
        }
#pragma unroll
        for (int i = 0; i < 8; ++i) {            // B: 2048 16B-chunks x2
            int id = tid + i * 256;
            int r = id >> 3, c = id & 7;
            uint32_t d = (uint32_t)r * (GAST * 4) + c * 16;
            size_t gb = (size_t)(n0 + r) * K + kt + c * 8;
            cpasync16(stBh + d, Bh + gb);
            cpasync16(stBl + d, Bl + gb);
        }
    };

    float acc[4][8][4];
#pragma unroll
    for (int mt = 0; mt < 4; ++mt)
#pragma unroll
        for (int nt = 0; nt < 8; ++nt)
#pragma unroll
            for (int q = 0; q < 4; ++q) acc[mt][nt][q] = 0.f;

    const int ntiles = K / 64;
    issue_stage(0, 0);  cp_commit();
    issue_stage(64, 1); cp_commit();
    cp_wait1();
    __syncthreads();

    for (int t = 0; t < ntiles; ++t) {
        const uint32_t* cA  = sm + (t & 1) * GSTG_U32;
        const uint32_t* cBh = cA + GA_U32;
        const uint32_t* cBl = cBh + GB_U32;

#pragma unroll
        for (int ks = 0; ks < 4; ++ks) {
            const int kb = ks * 8;
            uint32_t av[4][4], bh[8][2], bl[8][2];
#pragma unroll
            for (int mt = 0; mt < 4; ++mt) {
                int r = wm * 64 + mt * 16 + g;
                int i0 = r * GAST + kb + tg;
                int i1 = (r + 8) * GAST + kb + tg;
                av[mt][0] = cA[i0];     av[mt][1] = cA[i1];
                av[mt][2] = cA[i0 + 4]; av[mt][3] = cA[i1 + 4];
            }
#pragma unroll
            for (int nt = 0; nt < 8; ++nt) {
                int n = wn * 64 + nt * 8 + g;
                int i0 = n * GAST + kb + tg;
                bh[nt][0] = cBh[i0]; bh[nt][1] = cBh[i0 + 4];
                bl[nt][0] = cBl[i0]; bl[nt][1] = cBl[i0 + 4];
            }
#pragma unroll
            for (int mt = 0; mt < 4; ++mt)
#pragma unroll
                for (int nt = 0; nt < 8; ++nt)
                    mma16f(acc[mt][nt], av[mt], bh[nt]);   // hi*hi
#pragma unroll
            for (int mt = 0; mt < 4; ++mt)
#pragma unroll
                for (int nt = 0; nt < 8; ++nt)
                    mma16f(acc[mt][nt], av[mt], bl[nt]);   // hi*lo
        }

        __syncthreads();
        if (t + 2 < ntiles) issue_stage((t + 2) * 64, t & 1);
        cp_commit();
        cp_wait1();
        __syncthreads();
    }

    if (ropep != nullptr) {
        // qkv path: RoPE on q,k columns, fp16 output
        __half* Cm = (__half*)Cout;
#pragma unroll
        for (int mt = 0; mt < 4; ++mt)
#pragma unroll
            for (int nt = 0; nt < 8; ++nt) {
                int r = m0 + wm * 64 + mt * 16 + g;
                int c = n0 + wn * 64 + nt * 8 + tg * 2;
                float2 v0 = make_float2(acc[mt][nt][0], acc[mt][nt][1]);
                float2 v1 = make_float2(acc[mt][nt][2], acc[mt][nt][3]);
                if (c < 2 * Ct) {
                    int d = (c & (HDt - 1)) >> 1;
                    float2 cs0 = *(const float2*)(ropep + (size_t)((r & (Tt - 1)) * 64 + d) * 2);
                    float2 cs1 = *(const float2*)(ropep + (size_t)(((r + 8) & (Tt - 1)) * 64 + d) * 2);
                    v0 = make_float2(v0.x * cs0.x - v0.y * cs0.y,
                                     v0.y * cs0.x + v0.x * cs0.y);
                    v1 = make_float2(v1.x * cs1.x - v1.y * cs1.y,
                                     v1.y * cs1.x + v1.x * cs1.y);
                }
                *(uint32_t*)(Cm + (size_t)r * N + c) = packh2(v0.x, v0.y);
                *(uint32_t*)(Cm + (size_t)(r + 8) * N + c) = packh2(v1.x, v1.y);
            }
    } else {
        float* Cm = (float*)Cout;
#pragma unroll
        for (int mt = 0; mt < 4; ++mt)
#pragma unroll
            for (int nt = 0; nt < 8; ++nt) {
                int r = m0 + wm * 64 + mt * 16 + g;
                int c = n0 + wn * 64 + nt * 8 + tg * 2;
                *(float2*)(Cm + (size_t)r * N + c) =
                    make_float2(acc[mt][nt][0], acc[mt][nt][1]);
                *(float2*)(Cm + (size_t)(r + 8) * N + c) =
                    make_float2(acc[mt][nt][2], acc[mt][nt][3]);
            }
    }
}

// ---------------------------------------------------------------------------
// Flash attention, fp16 m16n8k16, causal. 1 block = (b, h, 128 q rows),
// 256 thr (8 warps x 16 rows). kv tile 64, double-buffered cp.async.
// P stays in registers (QK C-frag == PV A-frag after repack).
// ---------------------------------------------------------------------------
static constexpr int KVST = 68;                       // u32 row stride
static constexpr int KV_U32 = 64 * KVST;              // per K or V tile
static constexpr int KVSTG = 2 * KV_U32;              // K+V per stage
static constexpr int FLASH_SMEM = 2 * KVSTG * 4;      // 69632 B

__global__ __launch_bounds__(256, 1) void flash_kernel(
    const __half* __restrict__ qkv, __half* __restrict__ y)
{
    extern __shared__ uint32_t sm[];
    const uint32_t sbase = (uint32_t)__cvta_generic_to_shared(sm);

    const int tid = threadIdx.x;
    const int w = tid >> 5, lane = tid & 31;
    const int g = lane >> 2, tg = lane & 3;
    const int qt = (int)gridDim.x - 1 - (int)blockIdx.x;   // heavy tiles first
    const int bh = blockIdx.y;
    const int b = bh >> 4, h = bh & 15;
    const int q0 = qt * 128;
    const __half* base = qkv + (size_t)(b * Tt) * C3;
    const int qcol = h * HDt, kcol = Ct + h * HDt;
    const int wr0 = w * 16;
    const float scale = 0.0883883476483184f;  // 1/sqrt(128)

    // ---- Stage Q (two 64-row passes through buf1's K region), frags to regs
    uint32_t qf[8][4];
    {
        const uint32_t qstage = sbase + KVSTG * 4;    // buf1 K area
        uint32_t* Qs = sm + KVSTG;
#pragma unroll
        for (int pass = 0; pass < 2; ++pass) {
#pragma unroll
            for (int i = 0; i < 4; ++i) {
                int id = tid + i * 256;
                int r = id >> 4, c = id & 15;
                cpasync16(qstage + (uint32_t)r * (KVST * 4) + c * 16,
                          base + (size_t)(q0 + pass * 64 + r) * C3 + qcol + c * 8);
            }
            cp_commit(); cp_wait0();
            __syncthreads();
            if ((w >> 2) == pass) {
                int rl = (wr0 & 63) + g;
#pragma unroll
                for (int kk = 0; kk < 8; ++kk) {
                    int a0 = rl * KVST + kk * 8 + tg;
                    int a1 = (rl + 8) * KVST + kk * 8 + tg;
                    qf[kk][0] = Qs[a0];
                    qf[kk][1] = Qs[a1];
                    qf[kk][2] = Qs[a0 + 4];
                    qf[kk][3] = Qs[a1 + 4];
                }
            }
            __syncthreads();
        }
    }

    auto issue_kv = [&](int j, int s) {
        const uint32_t stK = sbase + (uint32_t)s * KVSTG * 4;
        const uint32_t stV = stK + KV_U32 * 4;
        const int kv0 = j * 64;
#pragma unroll
        for (int i = 0; i < 4; ++i) {
            int id = tid + i * 256;
            int r = id >> 4, c = id & 15;
            uint32_t d = (uint32_t)r * (KVST * 4) + c * 16;
            const __half* kp = base + (size_t)(kv0 + r) * C3 + kcol + c * 8;
            cpasync16(stK + d, kp);
            cpasync16(stV + d, kp + Ct);
        }
    };

    float m_a = -1e30f, m_b = -1e30f, l_a = 0.f, l_b = 0.f;
    float o[16][4];
#pragma unroll
    for (int nt = 0; nt < 16; ++nt)
#pragma unroll
        for (int q = 0; q < 4; ++q) o[nt][q] = 0.f;

    const int njt = 2 * qt + 2;
    issue_kv(0, 0); cp_commit();

    for (int j = 0; j < njt; ++j) {
        if (j + 1 < njt) issue_kv(j + 1, (j + 1) & 1);
        cp_commit();
        cp_wait1();          // tile j landed
        __syncthreads();

        const int kv0 = j * 64;
        const uint32_t* Ks = sm + (j & 1) * KVSTG;
        const uint32_t vbyte = sbase + (j & 1) * KVSTG * 4 + KV_U32 * 4;

        if (kv0 <= q0 + wr0 + 15) {          // warp-level causal skip
            float s[8][4];
#pragma unroll
            for (int nt = 0; nt < 8; ++nt)
#pragma unroll
                for (int q = 0; q < 4; ++q) s[nt][q] = 0.f;
            // S = Q @ K^T : 8 k-chunks x 8 kv-col tiles
#pragma unroll
            for (int kk = 0; kk < 8; ++kk) {
#pragma unroll
                for (int nt = 0; nt < 8; ++nt) {
                    uint32_t bb[2];
                    int i0 = (nt * 8 + g) * KVST + kk * 8 + tg;
                    bb[0] = Ks[i0];
                    bb[1] = Ks[i0 + 4];
                    mma16f(s[nt], qf[kk], bb);
                }
            }

#pragma unroll
            for (int nt = 0; nt < 8; ++nt)
#pragma unroll
                for (int q = 0; q < 4; ++q) s[nt][q] *= scale;

            if (kv0 + 63 > q0 + wr0) {       // diagonal tile: mask
                int ra = q0 + wr0 + g, rb = ra + 8;
#pragma unroll
                for (int nt = 0; nt < 8; ++nt) {
                    int c0 = kv0 + nt * 8 + tg * 2;
                    if (c0     > ra) s[nt][0] = -1e30f;
                    if (c0 + 1 > ra) s[nt][1] = -1e30f;
                    if (c0     > rb) s[nt][2] = -1e30f;
                    if (c0 + 1 > rb) s[nt][3] = -1e30f;
                }
            }

            // online softmax
            float tma = -1e30f, tmb = -1e30f;
#pragma unroll
            for (int nt = 0; nt < 8; ++nt) {
                tma = fmaxf(tma, fmaxf(s[nt][0], s[nt][1]));
                tmb = fmaxf(tmb, fmaxf(s[nt][2], s[nt][3]));
            }
            tma = fmaxf(tma, __shfl_xor_sync(0xffffffffu, tma, 1));
            tma = fmaxf(tma, __shfl_xor_sync(0xffffffffu, tma, 2));
            tmb = fmaxf(tmb, __shfl_xor_sync(0xffffffffu, tmb, 1));
            tmb = fmaxf(tmb, __shfl_xor_sync(0xffffffffu, tmb, 2));
            float mna = fmaxf(m_a, tma), mnb = fmaxf(m_b, tmb);
            float aa = __expf(m_a - mna), ab = __expf(m_b - mnb);
            float rsa = 0.f, rsb = 0.f;
#pragma unroll
            for (int nt = 0; nt < 8; ++nt) {
                s[nt][0] = __expf(s[nt][0] - mna);
                s[nt][1] = __expf(s[nt][1] - mna);
                s[nt][2] = __expf(s[nt][2] - mnb);
                s[nt][3] = __expf(s[nt][3] - mnb);
                rsa += s[nt][0] + s[nt][1];
                rsb += s[nt][2] + s[nt][3];
            }
            rsa += __shfl_xor_sync(0xffffffffu, rsa, 1);
            rsa += __shfl_xor_sync(0xffffffffu, rsa, 2);
            rsb += __shfl_xor_sync(0xffffffffu, rsb, 1);
            rsb += __shfl_xor_sync(0xffffffffu, rsb, 2);
            l_a = l_a * aa + rsa;
            l_b = l_b * ab + rsb;
            m_a = mna;
            m_b = mnb;
#pragma unroll
            for (int nt = 0; nt < 16; ++nt) {
                o[nt][0] *= aa; o[nt][1] *= aa;
                o[nt][2] *= ab; o[nt][3] *= ab;
            }

            // O += P @ V : P repacked in registers, V^T via ldmatrix.trans
#pragma unroll
            for (int kk = 0; kk < 4; ++kk) {
                uint32_t pa[4];
                pa[0] = packh2(s[2 * kk][0],     s[2 * kk][1]);
                pa[1] = packh2(s[2 * kk][2],     s[2 * kk][3]);
                pa[2] = packh2(s[2 * kk + 1][0], s[2 * kk + 1][1]);
                pa[3] = packh2(s[2 * kk + 1][2], s[2 * kk + 1][3]);
                uint32_t vrow = vbyte + (uint32_t)(kk * 16 + (lane & 15)) * (KVST * 4);
#pragma unroll
                for (int nt = 0; nt < 16; ++nt) {
                    uint32_t vb0, vb1;
                    ldsm_x2_t(vb0, vb1, vrow + nt * 16);
                    uint32_t bb[2] = {vb0, vb1};
                    mma16f(o[nt], pa, bb);
                }
            }
        }
        __syncthreads();     // all warps done with buf j before refill
    }

    // epilogue: normalize, fp16 y
    float inva = 1.f / l_a, invb = 1.f / l_b;
    int rt = b * Tt + q0 + wr0 + g;
#pragma unroll
    for (int nt = 0; nt < 16; ++nt) {
        int c = h * HDt + nt * 8 + tg * 2;
        *(uint32_t*)(y + (size_t)rt * Ct + c) =
            packh2(o[nt][0] * inva, o[nt][1] * inva);
        *(uint32_t*)(y + (size_t)(rt + 8) * Ct + c) =
            packh2(o[nt][2] * invb, o[nt][3] * invb);
    }
}

// ---------------------------------------------------------------------------
extern "C" void kernel_launch(void* const* d_in, const int* in_sizes, int n_in,
                              void* d_out, int out_size)
{
    const float* x     = (const float*)d_in[0];
    const float* rope  = (const float*)d_in[1];
    const float* Wqkv  = (const float*)d_in[2];
    const float* Wproj = (const float*)d_in[3];
    float* out = (float*)d_out;

    __half *qkv, *xh, *wqh, *wql, *wph, *wpl, *y;
    cudaGetSymbolAddress((void**)&qkv, g_qkv);
    cudaGetSymbolAddress((void**)&xh, g_xh);
    cudaGetSymbolAddress((void**)&wqh, g_wqh);
    cudaGetSymbolAddress((void**)&wql, g_wql);
    cudaGetSymbolAddress((void**)&wph, g_wph);
    cudaGetSymbolAddress((void**)&wpl, g_wpl);
    cudaGetSymbolAddress((void**)&y, g_y);

    cudaFuncSetAttribute(gemm_fp16x2, cudaFuncAttributeMaxDynamicSharedMemorySize,
                         GEMM_SMEM);
    cudaFuncSetAttribute(flash_kernel, cudaFuncAttributeMaxDynamicSharedMemorySize,
                         FLASH_SMEM);

    // 0) pre-pass: x -> fp16 ; W -> fp16 hi/lo transposed
    {
        size_t nx = (size_t)MTOT * Ct;
        tohalf_kernel<<<(unsigned)((nx + 255) / 256), 256>>>(x, xh, nx);
        split_transpose_kernel<<<dim3(C3 / 32, Ct / 32), dim3(32, 8)>>>(Wqkv, wqh, wql, Ct, C3);
        split_transpose_kernel<<<dim3(Ct / 32, Ct / 32), dim3(32, 8)>>>(Wproj, wph, wpl, Ct, Ct);
    }

    // 1) qkv = x @ Wqkv + fused RoPE, fp16 out  (M=8192, N=6144, K=2048)
    gemm_fp16x2<<<dim3(C3 / 256, MTOT / 128), 256, GEMM_SMEM>>>(
        xh, wqh, wql, qkv, MTOT, C3, Ct, rope);

    // 2) flash attention -> y (fp16)
    flash_kernel<<<dim3(Tt / 128, Bt * Ht), 256, FLASH_SMEM>>>(qkv, y);

    // 3) out = y @ Wproj, fp32 out  (M=8192, N=2048, K=2048)
    gemm_fp16x2<<<dim3(Ct / 256, MTOT / 128), 256, GEMM_SMEM>>>(
        y, wph, wpl, out, MTOT, Ct, Ct, nullptr);
}